// round 12
// baseline (speedup 1.0000x reference)
#include <cuda_runtime.h>
#include <cuda_fp16.h>
#include <mma.h>
#include <math.h>

#define Bb 4
#define Tt 1024
#define Dd 1024
#define Hh 16
#define HDh 64
#define LR 64
#define BT (Bb*Tt)             /* 4096 */
#define BTD ((long)BT*Dd)      /* 4194304 */
#define STATE (Bb*Hh*HDh*HDh)  /* 262144 */

// ---------------- scratch (device globals; no allocation allowed) ----------
__device__ __half g_dxh[BTD];
__device__ __half g_lerpx[BTD];
__device__ __half g_in[5*BTD];
__device__ __half g_t1[(long)BT*384];
__device__ float  g_s1p[2ll*BT*384];
__device__ __half g_t2[(long)BT*128];
__device__ __half g_laP[384*1024];
__device__ __half g_lbP[5*1024*64];
__device__ float  g_llP[5*1024];
__device__ __half g_W5[5ll*1024*1024];
__device__ float  g_w[BTD];
__device__ float  g_proj[4*BTD];
__device__ float  g_y[BTD];
__device__ __half g_opre[BTD];
__device__ float  g_stfb[STATE];
__device__ int    g_flag[3*32*8];      // rkv GEMM tile progress flags

__device__ __forceinline__ uint2 h4pack(float a, float b, float c, float d) {
    __half2 p0 = __floats2half2_rn(a, b);
    __half2 p1 = __floats2half2_rn(c, d);
    uint2 r;
    r.x = *reinterpret_cast<unsigned*>(&p0);
    r.y = *reinterpret_cast<unsigned*>(&p1);
    return r;
}

__device__ __forceinline__ void wait_flag(const int* f) {
    volatile const int* vf = f;
    while (*vf == 0) __nanosleep(200);
    __threadfence();
}

// ---------------- elementwise / pack kernels -------------------------------

__global__ void __launch_bounds__(256) clear_flags_kernel() {
    int i = blockIdx.x * 256 + threadIdx.x;
    if (i < 3 * 32 * 8) g_flag[i] = 0;
}

// vectorized: 4 elements per thread; dx stored as half
__global__ void __launch_bounds__(256) premix_kernel(
        const float* __restrict__ x, const float* __restrict__ xw,
        __half* __restrict__ dxh, __half* __restrict__ lerpx) {
    long idx = ((long)blockIdx.x * 256 + threadIdx.x) * 4;
    int dd = (int)(idx % Dd);
    long bt = idx / Dd;
    int t = (int)(bt % Tt);
    float4 xv = *(const float4*)&x[idx];
    float4 xp = make_float4(0.f, 0.f, 0.f, 0.f);
    if (t > 0) xp = *(const float4*)&x[idx - Dd];
    float4 wv = *(const float4*)&xw[dd];
    float4 d;
    d.x = xp.x - xv.x; d.y = xp.y - xv.y;
    d.z = xp.z - xv.z; d.w = xp.w - xv.w;
    uint2 dh = h4pack(d.x, d.y, d.z, d.w);
    *(uint2*)&dxh[idx] = dh;
    uint2 o = h4pack(fmaf(d.x, wv.x, xv.x), fmaf(d.y, wv.y, xv.y),
                     fmaf(d.z, wv.z, xv.z), fmaf(d.w, wv.w, xv.w));
    *(uint2*)&lerpx[idx] = o;
}

__global__ void __launch_bounds__(256) pack_la_kernel(
        const float* __restrict__ a0, const float* __restrict__ a1,
        const float* __restrict__ a2, const float* __restrict__ a3,
        const float* __restrict__ a4, __half* __restrict__ dst) {
    long i = (long)blockIdx.x * 256 + threadIdx.x;
    int row = (int)(i >> 10);
    int col = (int)(i & 1023);
    int p = row >> 6;
    float v = 0.f;
    if (p < 5) {
        const float* src = (p == 0) ? a0 : (p == 1) ? a1 : (p == 2) ? a2
                         : (p == 3) ? a3 : a4;
        v = src[(long)(row & 63) * 1024 + col];
    }
    dst[i] = __float2half_rn(v);
}

__global__ void __launch_bounds__(256) pack_lb_kernel(
        const float* __restrict__ b0, const float* __restrict__ b1,
        const float* __restrict__ b2, const float* __restrict__ b3,
        const float* __restrict__ b4, __half* __restrict__ dstb,
        const float* __restrict__ l0, const float* __restrict__ l1,
        const float* __restrict__ l2, const float* __restrict__ l3,
        const float* __restrict__ l4, float* __restrict__ dstl) {
    long i = (long)blockIdx.x * 256 + threadIdx.x;
    if (i < 5ll * 1024 * 64) {
        int p = (int)(i >> 16);
        long r = i & 65535;
        const float* src = (p == 0) ? b0 : (p == 1) ? b1 : (p == 2) ? b2
                         : (p == 3) ? b3 : b4;
        dstb[i] = __float2half_rn(src[r]);
    } else {
        int j = (int)(i - 5ll * 1024 * 64);
        int p = j >> 10;
        int r = j & 1023;
        const float* src = (p == 0) ? l0 : (p == 1) ? l1 : (p == 2) ? l2
                         : (p == 3) ? l3 : l4;
        dstl[j] = src[r];
    }
}

__global__ void __launch_bounds__(256) pack_w_kernel(
        const float* __restrict__ w0, const float* __restrict__ w1,
        const float* __restrict__ w2, const float* __restrict__ w3,
        const float* __restrict__ w4, __half* __restrict__ dst) {
    long i = (long)blockIdx.x * 256 + threadIdx.x;
    int p = (int)(i >> 20);
    long r = i & 1048575;
    const float* src = (p == 0) ? w0 : (p == 1) ? w1 : (p == 2) ? w2
                     : (p == 3) ? w3 : w4;
    dst[i] = __float2half_rn(src[r]);
}

__global__ void __launch_bounds__(256) combine_t1_kernel(
        const float* __restrict__ p, __half* __restrict__ dst) {
    long i = ((long)blockIdx.x * 256 + threadIdx.x) * 4;
    float4 a = *(const float4*)&p[i];
    float4 b = *(const float4*)&p[(long)BT * 384 + i];
    uint2 o = h4pack(tanhf(a.x + b.x), tanhf(a.y + b.y),
                     tanhf(a.z + b.z), tanhf(a.w + b.w));
    *(uint2*)&dst[i] = o;
}

// ---------------- fp16 tensor-core GEMM with fused epilogues ---------------
// PROVEN config: BKK=64, SLDH=72, 2-stage ping-pong, 2 CTAs/SM.
// MODE 0: Cf = acc (float out)   [optional per-tile progress flags]
// MODE 1: Ch = half(tanh(acc))
// MODE 2: Ch = half(x + dxh*(acc+L))
// MODE 3: Cf = exp(-exp(acc+L))
#define BKK 64
#define SLDH 72
#define PIPEH (2*128*SLDH)
#define GSMEM (2*PIPEH*2)

template<int MODE>
__global__ void __launch_bounds__(256, 2) gemm_h(
        const __half* __restrict__ A, long sAz, int lda,
        const __half* __restrict__ W, long sWz, int ldw,
        void* __restrict__ Cv, long sCz, int ldc,
        const float* __restrict__ L, long sLz,
        const float* __restrict__ x, const __half* __restrict__ dx,
        int K, int* flags) {
    using namespace nvcuda;
    extern __shared__ __half sm[];
    const int tid = threadIdx.x;
    const int z = blockIdx.z;
    A += (long)z * sAz;
    W += (long)z * sWz;
    if (MODE >= 2) L += (long)z * sLz;
    float* Cf = (float*)Cv + (long)z * sCz;
    __half* Ch = (__half*)Cv + (long)z * sCz;
    const int bm = blockIdx.y * 128;
    const int bn = blockIdx.x * 128;
    const int r = tid >> 3;
    const int q = (tid & 7) * 8;
    const __half* aP = A + (long)(bm + r) * lda + q;
    const __half* wP = W + (long)(bn + r) * ldw + q;
    unsigned dA = (unsigned)__cvta_generic_to_shared(sm) + (r * SLDH + q) * 2;
    const int wid = tid >> 5;
    const int wy = wid >> 1;
    const int wx = wid & 1;

    wmma::fragment<wmma::accumulator, 16, 16, 16, float> acc[2][4];
    #pragma unroll
    for (int i = 0; i < 2; i++)
        #pragma unroll
        for (int j = 0; j < 4; j++)
            wmma::fill_fragment(acc[i][j], 0.0f);

#define ISSUE(st, k0) do {                                                   \
        unsigned _a = dA + (st) * (PIPEH * 2);                               \
        unsigned _b = _a + 128 * SLDH * 2;                                   \
        _Pragma("unroll")                                                    \
        for (int _i = 0; _i < 4; _i++) {                                     \
            asm volatile("cp.async.cg.shared.global [%0], [%1], 16;\n" ::    \
                "r"(_a + _i * 32 * SLDH * 2),                                \
                "l"(aP + (long)_i * 32 * lda + (k0)));                       \
            asm volatile("cp.async.cg.shared.global [%0], [%1], 16;\n" ::    \
                "r"(_b + _i * 32 * SLDH * 2),                                \
                "l"(wP + (long)_i * 32 * ldw + (k0)));                       \
        }                                                                    \
        asm volatile("cp.async.commit_group;\n");                            \
    } while (0)

    const int nIter = K / BKK;
    ISSUE(0, 0);
    if (nIter > 1) {
        ISSUE(1, BKK);
        asm volatile("cp.async.wait_group 1;\n");
    } else {
        asm volatile("cp.async.wait_group 0;\n");
    }
    __syncthreads();

    for (int it = 0; it < nIter; it++) {
        int s = it & 1;
        const __half* sA = sm + s * PIPEH;
        const __half* sB = sA + 128 * SLDH;
        #pragma unroll
        for (int kk = 0; kk < BKK; kk += 16) {
            wmma::fragment<wmma::matrix_a, 16, 16, 16, __half, wmma::row_major> af[2];
            wmma::fragment<wmma::matrix_b, 16, 16, 16, __half, wmma::col_major> bf[4];
            #pragma unroll
            for (int i = 0; i < 2; i++)
                wmma::load_matrix_sync(af[i], sA + (wy * 32 + i * 16) * SLDH + kk, SLDH);
            #pragma unroll
            for (int j = 0; j < 4; j++)
                wmma::load_matrix_sync(bf[j], sB + (wx * 64 + j * 16) * SLDH + kk, SLDH);
            #pragma unroll
            for (int i = 0; i < 2; i++)
                #pragma unroll
                for (int j = 0; j < 4; j++)
                    wmma::mma_sync(acc[i][j], af[i], bf[j], acc[i][j]);
        }
        __syncthreads();
        if (it + 2 < nIter) {
            ISSUE(s, (it + 2) * BKK);
            asm volatile("cp.async.wait_group 1;\n");
            __syncthreads();
        } else if (it + 1 < nIter) {
            asm volatile("cp.async.wait_group 0;\n");
            __syncthreads();
        }
    }
#undef ISSUE

    if (MODE == 0) {
        #pragma unroll
        for (int i = 0; i < 2; i++)
            #pragma unroll
            for (int j = 0; j < 4; j++)
                wmma::store_matrix_sync(
                    Cf + (long)(bm + wy * 32 + i * 16) * ldc + bn + wx * 64 + j * 16,
                    acc[i][j], ldc, wmma::mem_row_major);
        if (flags != nullptr) {
            __threadfence();
            __syncthreads();
            if (tid == 0)
                flags[(z * 32 + blockIdx.y) * 8 + blockIdx.x] = 1;
        }
    } else {
        float* smf = reinterpret_cast<float*>(sm);
        __syncthreads();
        #pragma unroll
        for (int i = 0; i < 2; i++)
            #pragma unroll
            for (int j = 0; j < 4; j++)
                wmma::store_matrix_sync(
                    smf + (wy * 32 + i * 16) * 128 + wx * 64 + j * 16,
                    acc[i][j], 128, wmma::mem_row_major);
        __syncthreads();
        int row = tid >> 1;
        int c0 = (tid & 1) * 64;
        long gro = bm + row;
        #pragma unroll
        for (int i = 0; i < 16; i++) {
            int c = c0 + i * 4;
            float4 m = *(float4*)&smf[row * 128 + c];
            if (MODE == 1) {
                uint2 o = h4pack(tanhf(m.x), tanhf(m.y), tanhf(m.z), tanhf(m.w));
                *(uint2*)&Ch[gro * ldc + bn + c] = o;
            } else if (MODE == 2) {
                float4 lv = *(const float4*)&L[bn + c];
                long gi = gro * 1024 + bn + c;
                float4 xv = *(const float4*)&x[gi];
                uint2 dvp = *(const uint2*)&dx[gi];
                __half2 d01 = *reinterpret_cast<__half2*>(&dvp.x);
                __half2 d23 = *reinterpret_cast<__half2*>(&dvp.y);
                float2 f01 = __half22float2(d01);
                float2 f23 = __half22float2(d23);
                uint2 o = h4pack(fmaf(f01.x, m.x + lv.x, xv.x),
                                 fmaf(f01.y, m.y + lv.y, xv.y),
                                 fmaf(f23.x, m.z + lv.z, xv.z),
                                 fmaf(f23.y, m.w + lv.w, xv.w));
                *(uint2*)&Ch[gro * ldc + bn + c] = o;
            } else {
                float4 lv = *(const float4*)&L[bn + c];
                float4 o;
                o.x = expf(-expf(m.x + lv.x));
                o.y = expf(-expf(m.y + lv.y));
                o.z = expf(-expf(m.z + lv.z));
                o.w = expf(-expf(m.w + lv.w));
                *(float4*)&Cf[gro * ldc + bn + c] = o;
            }
        }
    }
}

// ---------------- recurrent scan: 128 CTAs, flag-synced with rkv GEMM ------
__global__ void __launch_bounds__(256) scan3_kernel(
        const float* __restrict__ r, const float* __restrict__ w,
        const float* __restrict__ k, const float* __restrict__ v,
        const float* __restrict__ init_state, const float* __restrict__ u,
        float* __restrict__ y, float* __restrict__ state_out,
        const int* __restrict__ flags) {
    int cta = blockIdx.x;
    int bh = cta >> 1, jh = cta & 1;
    int b = bh / Hh, h = bh % Hh;
    int tid = threadIdx.x;
    int j32 = tid & 31;
    int gi = tid >> 5;
    int j = jh * 32 + j32;
    int ntile = h >> 1;
    __shared__ float sh[2][224];
    __shared__ float ypart[2][8][32];
    float S[8], uu[8];
    #pragma unroll
    for (int ii = 0; ii < 8; ii++) {
        int i = gi * 8 + ii;
        S[ii] = init_state[(long)(h * 64 + i) * 64 + j];
        uu[ii] = u[h * 64 + i];
    }
    long base = (long)b * Tt * Dd + (long)h * 64;
    const float* myp = nullptr;
    int myz = -1;                       // which proj flag this loader needs
    if (tid < 64)       { myp = r + base + tid;                   myz = 0; }
    else if (tid < 128) { myp = w + base + (tid - 64);            myz = -1; }
    else if (tid < 192) { myp = k + base + (tid - 128);           myz = 1; }
    else if (tid < 224) { myp = v + base + jh * 32 + (tid - 192); myz = 2; }

    // prologue: wait for tile 0 of this (b, ntile), stage t=0, prefetch t=1
    if (myz >= 0) wait_flag(&flags[(myz * 32 + b * 8) * 8 + ntile]);
    if (tid < 224) sh[0][tid] = myp[0];
    __syncthreads();
    float pref = (tid < 224) ? myp[Dd] : 0.f;

    for (int t = 0; t < Tt; t++) {
        int cur = t & 1, nxt = cur ^ 1;
        float vj = sh[cur][192 + j32];
        float acc = 0.f;
        #pragma unroll
        for (int ii = 0; ii < 8; ii++) {
            int i = gi * 8 + ii;
            float kv = sh[cur][128 + i] * vj;
            acc = fmaf(sh[cur][i], fmaf(uu[ii], kv, S[ii]), acc);
            S[ii] = fmaf(sh[cur][64 + i], S[ii], kv);
        }
        ypart[cur][gi][j32] = acc;
        if (tid < 224) {
            sh[nxt][tid] = pref;
            int tn = t + 2;
            if (tn < Tt) {
                if ((tn & 127) == 0 && myz >= 0)
                    wait_flag(&flags[(myz * 32 + b * 8 + (tn >> 7)) * 8 + ntile]);
                pref = myp[(long)tn * Dd];
            }
        }
        __syncthreads();
        if (gi == 0) {
            float yy = 0.f;
            #pragma unroll
            for (int g2 = 0; g2 < 8; g2++) yy += ypart[cur][g2][j32];
            y[base + (long)t * Dd + j] = yy;
        }
    }
    #pragma unroll
    for (int ii = 0; ii < 8; ii++) {
        int i = gi * 8 + ii;
        state_out[(long)((b * Hh + h) * 64 + i) * 64 + j] = S[ii];
    }
}

// ---------------- groupnorm + silu gate ------------------------------------
__global__ void __launch_bounds__(256) gn_gate_kernel(
        const float* __restrict__ y, const float* __restrict__ g,
        const float* __restrict__ lnw, const float* __restrict__ lnb,
        __half* __restrict__ out) {
    long warp = ((long)blockIdx.x * blockDim.x + threadIdx.x) >> 5;
    int lane = threadIdx.x & 31;
    if (warp >= (long)Bb * Tt * Hh) return;
    const float* yp = y + warp * 64;
    float v0 = yp[lane], v1 = yp[lane + 32];
    float s = v0 + v1;
    #pragma unroll
    for (int off = 16; off > 0; off >>= 1) s += __shfl_xor_sync(0xffffffffu, s, off);
    float mean = s * (1.f / 64.f);
    float d0 = v0 - mean, d1 = v1 - mean;
    float vs = d0 * d0 + d1 * d1;
    #pragma unroll
    for (int off = 16; off > 0; off >>= 1) vs += __shfl_xor_sync(0xffffffffu, vs, off);
    float inv = rsqrtf(vs * (1.f / 64.f) + 1e-5f);
    float n0 = fmaf(d0 * inv, lnw[lane], lnb[lane]);
    float n1 = fmaf(d1 * inv, lnw[lane + 32], lnb[lane + 32]);
    float g0 = g[warp * 64 + lane];
    float g1 = g[warp * 64 + lane + 32];
    float s0 = g0 / (1.f + expf(-g0));
    float s1 = g1 / (1.f + expf(-g1));
    out[warp * 64 + lane] = __float2half_rn(s0 * n0);
    out[warp * 64 + lane + 32] = __float2half_rn(s1 * n1);
}

// ---------------- host -----------------------------------------------------
static void* symaddr(const void* s) {
    void* p = nullptr;
    cudaGetSymbolAddress(&p, s);
    return p;
}

extern "C" void kernel_launch(void* const* d_in, const int* in_sizes, int n_in,
                              void* d_out, int out_size) {
    (void)in_sizes; (void)n_in;
    const float* x    = (const float*)d_in[0];
    const float* xw   = (const float*)d_in[1];
    const float* rW   = (const float*)d_in[2];
    const float* kW   = (const float*)d_in[3];
    const float* vW   = (const float*)d_in[4];
    const float* gW   = (const float*)d_in[5];
    const float* la[5] = {(const float*)d_in[6],  (const float*)d_in[9],
                          (const float*)d_in[12], (const float*)d_in[15],
                          (const float*)d_in[18]};
    const float* lb[5] = {(const float*)d_in[7],  (const float*)d_in[10],
                          (const float*)d_in[13], (const float*)d_in[16],
                          (const float*)d_in[19]};
    const float* ll[5] = {(const float*)d_in[8],  (const float*)d_in[11],
                          (const float*)d_in[14], (const float*)d_in[17],
                          (const float*)d_in[20]};
    const float* ln_w = (const float*)d_in[21];
    const float* ln_b = (const float*)d_in[22];
    const float* oW   = (const float*)d_in[23];
    const float* init_state = (const float*)d_in[24];
    const float* u    = (const float*)d_in[25];

    float* out = (float*)d_out;

    __half* p_dxh   = (__half*)symaddr(g_dxh);
    __half* p_lerpx = (__half*)symaddr(g_lerpx);
    __half* p_in    = (__half*)symaddr(g_in);
    __half* p_t1    = (__half*)symaddr(g_t1);
    float*  p_s1p   = (float*)symaddr(g_s1p);
    __half* p_t2    = (__half*)symaddr(g_t2);
    __half* p_laP   = (__half*)symaddr(g_laP);
    __half* p_lbP   = (__half*)symaddr(g_lbP);
    float*  p_llP   = (float*)symaddr(g_llP);
    __half* p_W5    = (__half*)symaddr(g_W5);
    float*  p_w     = (float*)symaddr(g_w);
    float*  p_proj  = (float*)symaddr(g_proj);
    float*  p_y     = (float*)symaddr(g_y);
    __half* p_opre  = (__half*)symaddr(g_opre);
    float*  p_stfb  = (float*)symaddr(g_stfb);
    int*    p_flag  = (int*)symaddr(g_flag);

    static cudaStream_t sA = nullptr, sB = nullptr;
    static cudaEvent_t eF = nullptr, eW = nullptr, eL = nullptr,
                       eWG = nullptr, eG = nullptr, eB = nullptr,
                       eC = nullptr, eS = nullptr;
    if (!sA) {
        cudaStreamCreateWithFlags(&sA, cudaStreamNonBlocking);
        cudaStreamCreateWithFlags(&sB, cudaStreamNonBlocking);
        cudaEventCreateWithFlags(&eF, cudaEventDisableTiming);
        cudaEventCreateWithFlags(&eW, cudaEventDisableTiming);
        cudaEventCreateWithFlags(&eL, cudaEventDisableTiming);
        cudaEventCreateWithFlags(&eWG, cudaEventDisableTiming);
        cudaEventCreateWithFlags(&eG, cudaEventDisableTiming);
        cudaEventCreateWithFlags(&eB, cudaEventDisableTiming);
        cudaEventCreateWithFlags(&eC, cudaEventDisableTiming);
        cudaEventCreateWithFlags(&eS, cudaEventDisableTiming);
        cudaFuncSetAttribute(gemm_h<0>, cudaFuncAttributeMaxDynamicSharedMemorySize, GSMEM);
        cudaFuncSetAttribute(gemm_h<1>, cudaFuncAttributeMaxDynamicSharedMemorySize, GSMEM);
        cudaFuncSetAttribute(gemm_h<2>, cudaFuncAttributeMaxDynamicSharedMemorySize, GSMEM);
        cudaFuncSetAttribute(gemm_h<3>, cudaFuncAttributeMaxDynamicSharedMemorySize, GSMEM);
    }

    // ---- forks: packs run off the critical path
    cudaEventRecord(eF, 0);
    cudaStreamWaitEvent(sA, eF, 0);
    pack_w_kernel<<<(5 * 1024 * 1024) / 256, 256, 0, sA>>>(rW, kW, vW, gW, oW, p_W5);
    cudaEventRecord(eW, sA);
    cudaStreamWaitEvent(sB, eF, 0);
    pack_la_kernel<<<(384 * 1024) / 256, 256, 0, sB>>>(la[0], la[1], la[2], la[3], la[4], p_laP);
    pack_lb_kernel<<<(5 * 1024 * 64 + 5 * 1024 + 255) / 256, 256, 0, sB>>>(
        lb[0], lb[1], lb[2], lb[3], lb[4], p_lbP,
        ll[0], ll[1], ll[2], ll[3], ll[4], p_llP);
    cudaEventRecord(eB, sB);

    // ---- main chain
    premix_kernel<<<(int)(BTD / 1024), 256>>>(x, xw, p_dxh, p_lerpx);

    // lora stage 1, split-K z=2
    cudaStreamWaitEvent(0, eB, 0);
    gemm_h<0><<<dim3(3, 32, 2), 256, GSMEM>>>(
        p_lerpx, 512, 1024, p_laP, 512, 1024, p_s1p, (long)BT * 384, 384,
        nullptr, 0, nullptr, nullptr, 512, nullptr);
    combine_t1_kernel<<<(BT * 384) / 1024, 256>>>(p_s1p, p_t1);

    // fused lora stage 2 + mix, all 5 paths
    gemm_h<2><<<dim3(8, 32, 5), 256, GSMEM>>>(
        p_t1, 64, 384, p_lbP, 65536, 64, p_in, BTD, 1024,
        p_llP, 1024, x, p_dxh, 64, nullptr);

    // ---- fork: d-lora second pass (t2, w) then g-projection on sA
    cudaEventRecord(eL, 0);
    cudaStreamWaitEvent(sA, eL, 0);
    gemm_h<1><<<dim3(1, 32, 1), 256, GSMEM, sA>>>(
        p_in + 4 * BTD, 0, 1024, p_laP + 256 * 1024, 0, 1024, p_t2, 0, 128,
        nullptr, 0, nullptr, nullptr, 1024, nullptr);
    gemm_h<3><<<dim3(8, 32, 1), 256, GSMEM, sA>>>(
        p_t2, 0, 128, p_lbP + 4 * 65536, 0, 64, p_w, 0, 1024,
        p_llP + 4 * 1024, 0, nullptr, nullptr, 64, nullptr);
    cudaEventRecord(eWG, sA);
    gemm_h<0><<<dim3(8, 32, 1), 256, GSMEM, sA>>>(
        p_in + 3 * BTD, 0, 1024, p_W5 + 3ll * 1024 * 1024, 0, 1024,
        p_proj + 3 * BTD, 0, 1024, nullptr, 0, nullptr, nullptr, 1024, nullptr);
    cudaEventRecord(eG, sA);

    // ---- r,k,v projections with progress flags; scan overlaps via flags
    cudaStreamWaitEvent(0, eW, 0);
    clear_flags_kernel<<<3, 256>>>();
    cudaEventRecord(eC, 0);
    gemm_h<0><<<dim3(8, 32, 3), 256, GSMEM>>>(
        p_in, BTD, 1024, p_W5, 1024 * 1024, 1024, p_proj, BTD, 1024,
        nullptr, 0, nullptr, nullptr, 1024, p_flag);

    cudaStreamWaitEvent(sB, eC, 0);
    cudaStreamWaitEvent(sB, eWG, 0);
    float* st_out = (out_size >= (int)(BTD + STATE)) ? (out + BTD) : p_stfb;
    scan3_kernel<<<2 * Bb * Hh, 256, 0, sB>>>(
        p_proj, p_w, p_proj + BTD, p_proj + 2 * BTD,
        init_state, u, p_y, st_out, p_flag);
    cudaEventRecord(eS, sB);

    // ---- gate (needs scan + g) + output projection
    cudaStreamWaitEvent(0, eS, 0);
    cudaStreamWaitEvent(0, eG, 0);
    gn_gate_kernel<<<(Bb * Tt * Hh) / 8, 256>>>(p_y, p_proj + 3 * BTD, ln_w, ln_b, p_opre);
    gemm_h<0><<<dim3(8, 32, 1), 256, GSMEM>>>(
        p_opre, 0, 1024, p_W5 + 4ll * 1024 * 1024, 0, 1024, out, 0, 1024,
        nullptr, 0, nullptr, nullptr, 1024, nullptr);
}

// round 13
// speedup vs baseline: 1.1661x; 1.1661x over previous
#include <cuda_runtime.h>
#include <cuda_fp16.h>
#include <mma.h>
#include <math.h>

#define Bb 4
#define Tt 1024
#define Dd 1024
#define Hh 16
#define HDh 64
#define LR 64
#define BT (Bb*Tt)             /* 4096 */
#define BTD ((long)BT*Dd)      /* 4194304 */
#define STATE (Bb*Hh*HDh*HDh)  /* 262144 */

// ---------------- scratch (device globals; no allocation allowed) ----------
__device__ float  g_dx[BTD];
__device__ __half g_lerpx[BTD];
__device__ __half g_in[5*BTD];
__device__ __half g_t1[(long)BT*384];
__device__ float  g_s1p[2ll*BT*384];   // split-K partials for stage1
__device__ __half g_t2[(long)BT*128];
__device__ __half g_laP[384*1024];
__device__ __half g_lbP[5*1024*64];
__device__ float  g_llP[5*1024];
__device__ __half g_W5[5ll*1024*1024];
__device__ float  g_w[BTD];
__device__ float  g_proj[4*BTD];
__device__ float  g_y[BTD];
__device__ __half g_opre[BTD];
__device__ float  g_stfb[STATE];

__device__ __forceinline__ uint2 h4pack(float a, float b, float c, float d) {
    __half2 p0 = __floats2half2_rn(a, b);
    __half2 p1 = __floats2half2_rn(c, d);
    uint2 r;
    r.x = *reinterpret_cast<unsigned*>(&p0);
    r.y = *reinterpret_cast<unsigned*>(&p1);
    return r;
}

// ---------------- elementwise / pack kernels -------------------------------

// vectorized: 4 elements per thread
__global__ void __launch_bounds__(256) premix_kernel(
        const float* __restrict__ x, const float* __restrict__ xw,
        float* __restrict__ dx, __half* __restrict__ lerpx) {
    long idx = ((long)blockIdx.x * 256 + threadIdx.x) * 4;
    int dd = (int)(idx % Dd);
    long bt = idx / Dd;
    int t = (int)(bt % Tt);
    float4 xv = *(const float4*)&x[idx];
    float4 xp = make_float4(0.f, 0.f, 0.f, 0.f);
    if (t > 0) xp = *(const float4*)&x[idx - Dd];
    float4 wv = *(const float4*)&xw[dd];
    float4 d;
    d.x = xp.x - xv.x; d.y = xp.y - xv.y;
    d.z = xp.z - xv.z; d.w = xp.w - xv.w;
    *(float4*)&dx[idx] = d;
    uint2 o = h4pack(fmaf(d.x, wv.x, xv.x), fmaf(d.y, wv.y, xv.y),
                     fmaf(d.z, wv.z, xv.z), fmaf(d.w, wv.w, xv.w));
    *(uint2*)&lerpx[idx] = o;
}

__global__ void __launch_bounds__(256) pack_la_kernel(
        const float* __restrict__ a0, const float* __restrict__ a1,
        const float* __restrict__ a2, const float* __restrict__ a3,
        const float* __restrict__ a4, __half* __restrict__ dst) {
    long i = (long)blockIdx.x * 256 + threadIdx.x;
    int row = (int)(i >> 10);
    int col = (int)(i & 1023);
    int p = row >> 6;
    float v = 0.f;
    if (p < 5) {
        const float* src = (p == 0) ? a0 : (p == 1) ? a1 : (p == 2) ? a2
                         : (p == 3) ? a3 : a4;
        v = src[(long)(row & 63) * 1024 + col];
    }
    dst[i] = __float2half_rn(v);
}

__global__ void __launch_bounds__(256) pack_lb_kernel(
        const float* __restrict__ b0, const float* __restrict__ b1,
        const float* __restrict__ b2, const float* __restrict__ b3,
        const float* __restrict__ b4, __half* __restrict__ dstb,
        const float* __restrict__ l0, const float* __restrict__ l1,
        const float* __restrict__ l2, const float* __restrict__ l3,
        const float* __restrict__ l4, float* __restrict__ dstl) {
    long i = (long)blockIdx.x * 256 + threadIdx.x;   // 5*1024*64 + 5*1024
    if (i < 5ll * 1024 * 64) {
        int p = (int)(i >> 16);
        long r = i & 65535;
        const float* src = (p == 0) ? b0 : (p == 1) ? b1 : (p == 2) ? b2
                         : (p == 3) ? b3 : b4;
        dstb[i] = __float2half_rn(src[r]);
    } else {
        int j = (int)(i - 5ll * 1024 * 64);
        int p = j >> 10;
        int r = j & 1023;
        const float* src = (p == 0) ? l0 : (p == 1) ? l1 : (p == 2) ? l2
                         : (p == 3) ? l3 : l4;
        dstl[j] = src[r];
    }
}

__global__ void __launch_bounds__(256) pack_w_kernel(
        const float* __restrict__ w0, const float* __restrict__ w1,
        const float* __restrict__ w2, const float* __restrict__ w3,
        const float* __restrict__ w4, __half* __restrict__ dst) {
    long i = (long)blockIdx.x * 256 + threadIdx.x;
    int p = (int)(i >> 20);
    long r = i & 1048575;
    const float* src = (p == 0) ? w0 : (p == 1) ? w1 : (p == 2) ? w2
                     : (p == 3) ? w3 : w4;
    dst[i] = __float2half_rn(src[r]);
}

// t1 = half(tanh(p0 + p1))   (combine split-K partials)
__global__ void __launch_bounds__(256) combine_t1_kernel(
        const float* __restrict__ p, __half* __restrict__ dst) {
    long i = ((long)blockIdx.x * 256 + threadIdx.x) * 4;
    float4 a = *(const float4*)&p[i];
    float4 b = *(const float4*)&p[(long)BT * 384 + i];
    uint2 o = h4pack(tanhf(a.x + b.x), tanhf(a.y + b.y),
                     tanhf(a.z + b.z), tanhf(a.w + b.w));
    *(uint2*)&dst[i] = o;
}

// ---------------- fp16 tensor-core GEMM with fused epilogues ---------------
// PROVEN config: BKK=64, SLDH=72, 2-stage ping-pong, 2 CTAs/SM.
// MODE 0: Cf = acc                    (float out)
// MODE 1: Ch = half(tanh(acc))        (half out)
// MODE 2: Ch = half(x + dx*(acc+L))   (half out; x/dx row length 1024)
// MODE 3: Cf = exp(-exp(acc+L))       (float out)
#define BKK 64
#define SLDH 72
#define PIPEH (2*128*SLDH)
#define GSMEM (2*PIPEH*2)

template<int MODE>
__global__ void __launch_bounds__(256) gemm_h(
        const __half* __restrict__ A, long sAz, int lda,
        const __half* __restrict__ W, long sWz, int ldw,
        void* __restrict__ Cv, long sCz, int ldc,
        const float* __restrict__ L, long sLz,
        const float* __restrict__ x, const float* __restrict__ dx,
        int K) {
    using namespace nvcuda;
    extern __shared__ __half sm[];
    const int tid = threadIdx.x;
    const int z = blockIdx.z;
    A += (long)z * sAz;
    W += (long)z * sWz;
    if (MODE >= 2) L += (long)z * sLz;
    float* Cf = (float*)Cv + (long)z * sCz;
    __half* Ch = (__half*)Cv + (long)z * sCz;
    const int bm = blockIdx.y * 128;
    const int bn = blockIdx.x * 128;
    const int r = tid >> 3;
    const int q = (tid & 7) * 8;
    const __half* aP = A + (long)(bm + r) * lda + q;
    const __half* wP = W + (long)(bn + r) * ldw + q;
    unsigned dA = (unsigned)__cvta_generic_to_shared(sm) + (r * SLDH + q) * 2;
    const int wid = tid >> 5;
    const int wy = wid >> 1;
    const int wx = wid & 1;

    wmma::fragment<wmma::accumulator, 16, 16, 16, float> acc[2][4];
    #pragma unroll
    for (int i = 0; i < 2; i++)
        #pragma unroll
        for (int j = 0; j < 4; j++)
            wmma::fill_fragment(acc[i][j], 0.0f);

#define ISSUE(st, k0) do {                                                   \
        unsigned _a = dA + (st) * (PIPEH * 2);                               \
        unsigned _b = _a + 128 * SLDH * 2;                                   \
        _Pragma("unroll")                                                    \
        for (int _i = 0; _i < 4; _i++) {                                     \
            asm volatile("cp.async.cg.shared.global [%0], [%1], 16;\n" ::    \
                "r"(_a + _i * 32 * SLDH * 2),                                \
                "l"(aP + (long)_i * 32 * lda + (k0)));                       \
            asm volatile("cp.async.cg.shared.global [%0], [%1], 16;\n" ::    \
                "r"(_b + _i * 32 * SLDH * 2),                                \
                "l"(wP + (long)_i * 32 * ldw + (k0)));                       \
        }                                                                    \
        asm volatile("cp.async.commit_group;\n");                            \
    } while (0)

    const int nIter = K / BKK;
    ISSUE(0, 0);
    if (nIter > 1) {
        ISSUE(1, BKK);
        asm volatile("cp.async.wait_group 1;\n");
    } else {
        asm volatile("cp.async.wait_group 0;\n");
    }
    __syncthreads();

    for (int it = 0; it < nIter; it++) {
        int s = it & 1;
        const __half* sA = sm + s * PIPEH;
        const __half* sB = sA + 128 * SLDH;
        #pragma unroll
        for (int kk = 0; kk < BKK; kk += 16) {
            wmma::fragment<wmma::matrix_a, 16, 16, 16, __half, wmma::row_major> af[2];
            wmma::fragment<wmma::matrix_b, 16, 16, 16, __half, wmma::col_major> bf[4];
            #pragma unroll
            for (int i = 0; i < 2; i++)
                wmma::load_matrix_sync(af[i], sA + (wy * 32 + i * 16) * SLDH + kk, SLDH);
            #pragma unroll
            for (int j = 0; j < 4; j++)
                wmma::load_matrix_sync(bf[j], sB + (wx * 64 + j * 16) * SLDH + kk, SLDH);
            #pragma unroll
            for (int i = 0; i < 2; i++)
                #pragma unroll
                for (int j = 0; j < 4; j++)
                    wmma::mma_sync(acc[i][j], af[i], bf[j], acc[i][j]);
        }
        __syncthreads();
        if (it + 2 < nIter) {
            ISSUE(s, (it + 2) * BKK);
            asm volatile("cp.async.wait_group 1;\n");
            __syncthreads();
        } else if (it + 1 < nIter) {
            asm volatile("cp.async.wait_group 0;\n");
            __syncthreads();
        }
    }
#undef ISSUE

    if (MODE == 0) {
        #pragma unroll
        for (int i = 0; i < 2; i++)
            #pragma unroll
            for (int j = 0; j < 4; j++)
                wmma::store_matrix_sync(
                    Cf + (long)(bm + wy * 32 + i * 16) * ldc + bn + wx * 64 + j * 16,
                    acc[i][j], ldc, wmma::mem_row_major);
    } else {
        float* smf = reinterpret_cast<float*>(sm);
        __syncthreads();
        #pragma unroll
        for (int i = 0; i < 2; i++)
            #pragma unroll
            for (int j = 0; j < 4; j++)
                wmma::store_matrix_sync(
                    smf + (wy * 32 + i * 16) * 128 + wx * 64 + j * 16,
                    acc[i][j], 128, wmma::mem_row_major);
        __syncthreads();
        int row = tid >> 1;
        int c0 = (tid & 1) * 64;
        long gro = bm + row;
        #pragma unroll
        for (int i = 0; i < 16; i++) {
            int c = c0 + i * 4;
            float4 m = *(float4*)&smf[row * 128 + c];
            if (MODE == 1) {
                uint2 o = h4pack(tanhf(m.x), tanhf(m.y), tanhf(m.z), tanhf(m.w));
                *(uint2*)&Ch[gro * ldc + bn + c] = o;
            } else if (MODE == 2) {
                float4 lv = *(const float4*)&L[bn + c];
                long gi = gro * 1024 + bn + c;
                float4 xv = *(const float4*)&x[gi];
                float4 dv = *(const float4*)&dx[gi];
                uint2 o = h4pack(fmaf(dv.x, m.x + lv.x, xv.x),
                                 fmaf(dv.y, m.y + lv.y, xv.y),
                                 fmaf(dv.z, m.z + lv.z, xv.z),
                                 fmaf(dv.w, m.w + lv.w, xv.w));
                *(uint2*)&Ch[gro * ldc + bn + c] = o;
            } else {
                float4 lv = *(const float4*)&L[bn + c];
                float4 o;
                o.x = expf(-expf(m.x + lv.x));
                o.y = expf(-expf(m.y + lv.y));
                o.z = expf(-expf(m.z + lv.z));
                o.w = expf(-expf(m.w + lv.w));
                *(float4*)&Cf[gro * ldc + bn + c] = o;
            }
        }
    }
}

// ---------------- recurrent scan: 128 CTAs, ONE sync per timestep ----------
__global__ void __launch_bounds__(256) scan3_kernel(
        const float* __restrict__ r, const float* __restrict__ w,
        const float* __restrict__ k, const float* __restrict__ v,
        const float* __restrict__ init_state, const float* __restrict__ u,
        float* __restrict__ y, float* __restrict__ state_out) {
    int cta = blockIdx.x;
    int bh = cta >> 1, jh = cta & 1;
    int b = bh / Hh, h = bh % Hh;
    int tid = threadIdx.x;
    int j32 = tid & 31;
    int gi = tid >> 5;
    int j = jh * 32 + j32;
    __shared__ float sh[2][224];
    __shared__ float ypart[2][8][32];
    float S[8], uu[8];
    #pragma unroll
    for (int ii = 0; ii < 8; ii++) {
        int i = gi * 8 + ii;
        S[ii] = init_state[(long)(h * 64 + i) * 64 + j];
        uu[ii] = u[h * 64 + i];
    }
    long base = (long)b * Tt * Dd + (long)h * 64;
    const float* myp = nullptr;
    if (tid < 64)       myp = r + base + tid;
    else if (tid < 128) myp = w + base + (tid - 64);
    else if (tid < 192) myp = k + base + (tid - 128);
    else if (tid < 224) myp = v + base + jh * 32 + (tid - 192);

    if (tid < 224) sh[0][tid] = myp[0];
    __syncthreads();
    float pref = (tid < 224) ? myp[Dd] : 0.f;

    for (int t = 0; t < Tt; t++) {
        int cur = t & 1, nxt = cur ^ 1;
        float vj = sh[cur][192 + j32];
        float acc = 0.f;
        #pragma unroll
        for (int ii = 0; ii < 8; ii++) {
            int i = gi * 8 + ii;
            float kv = sh[cur][128 + i] * vj;
            acc = fmaf(sh[cur][i], fmaf(uu[ii], kv, S[ii]), acc);
            S[ii] = fmaf(sh[cur][64 + i], S[ii], kv);
        }
        ypart[cur][gi][j32] = acc;
        if (tid < 224) {
            sh[nxt][tid] = pref;
            if (t + 2 < Tt) pref = myp[(long)(t + 2) * Dd];
        }
        __syncthreads();
        if (gi == 0) {
            float yy = 0.f;
            #pragma unroll
            for (int g2 = 0; g2 < 8; g2++) yy += ypart[cur][g2][j32];
            y[base + (long)t * Dd + j] = yy;
        }
    }
    #pragma unroll
    for (int ii = 0; ii < 8; ii++) {
        int i = gi * 8 + ii;
        state_out[(long)((b * Hh + h) * 64 + i) * 64 + j] = S[ii];
    }
}

// ---------------- groupnorm + silu gate ------------------------------------
__global__ void __launch_bounds__(256) gn_gate_kernel(
        const float* __restrict__ y, const float* __restrict__ g,
        const float* __restrict__ lnw, const float* __restrict__ lnb,
        __half* __restrict__ out) {
    long warp = ((long)blockIdx.x * blockDim.x + threadIdx.x) >> 5;
    int lane = threadIdx.x & 31;
    if (warp >= (long)Bb * Tt * Hh) return;
    const float* yp = y + warp * 64;
    float v0 = yp[lane], v1 = yp[lane + 32];
    float s = v0 + v1;
    #pragma unroll
    for (int off = 16; off > 0; off >>= 1) s += __shfl_xor_sync(0xffffffffu, s, off);
    float mean = s * (1.f / 64.f);
    float d0 = v0 - mean, d1 = v1 - mean;
    float vs = d0 * d0 + d1 * d1;
    #pragma unroll
    for (int off = 16; off > 0; off >>= 1) vs += __shfl_xor_sync(0xffffffffu, vs, off);
    float inv = rsqrtf(vs * (1.f / 64.f) + 1e-5f);
    float n0 = fmaf(d0 * inv, lnw[lane], lnb[lane]);
    float n1 = fmaf(d1 * inv, lnw[lane + 32], lnb[lane + 32]);
    float g0 = g[warp * 64 + lane];
    float g1 = g[warp * 64 + lane + 32];
    float s0 = g0 / (1.f + expf(-g0));
    float s1 = g1 / (1.f + expf(-g1));
    out[warp * 64 + lane] = __float2half_rn(s0 * n0);
    out[warp * 64 + lane + 32] = __float2half_rn(s1 * n1);
}

// ---------------- host -----------------------------------------------------
static void* symaddr(const void* s) {
    void* p = nullptr;
    cudaGetSymbolAddress(&p, s);
    return p;
}

extern "C" void kernel_launch(void* const* d_in, const int* in_sizes, int n_in,
                              void* d_out, int out_size) {
    (void)in_sizes; (void)n_in;
    const float* x    = (const float*)d_in[0];
    const float* xw   = (const float*)d_in[1];
    const float* rW   = (const float*)d_in[2];
    const float* kW   = (const float*)d_in[3];
    const float* vW   = (const float*)d_in[4];
    const float* gW   = (const float*)d_in[5];
    const float* la[5] = {(const float*)d_in[6],  (const float*)d_in[9],
                          (const float*)d_in[12], (const float*)d_in[15],
                          (const float*)d_in[18]};
    const float* lb[5] = {(const float*)d_in[7],  (const float*)d_in[10],
                          (const float*)d_in[13], (const float*)d_in[16],
                          (const float*)d_in[19]};
    const float* ll[5] = {(const float*)d_in[8],  (const float*)d_in[11],
                          (const float*)d_in[14], (const float*)d_in[17],
                          (const float*)d_in[20]};
    const float* ln_w = (const float*)d_in[21];
    const float* ln_b = (const float*)d_in[22];
    const float* oW   = (const float*)d_in[23];
    const float* init_state = (const float*)d_in[24];
    const float* u    = (const float*)d_in[25];

    float* out = (float*)d_out;

    float*  p_dx    = (float*)symaddr(g_dx);
    __half* p_lerpx = (__half*)symaddr(g_lerpx);
    __half* p_in    = (__half*)symaddr(g_in);
    __half* p_t1    = (__half*)symaddr(g_t1);
    float*  p_s1p   = (float*)symaddr(g_s1p);
    __half* p_t2    = (__half*)symaddr(g_t2);
    __half* p_laP   = (__half*)symaddr(g_laP);
    __half* p_lbP   = (__half*)symaddr(g_lbP);
    float*  p_llP   = (float*)symaddr(g_llP);
    __half* p_W5    = (__half*)symaddr(g_W5);
    float*  p_w     = (float*)symaddr(g_w);
    float*  p_proj  = (float*)symaddr(g_proj);
    float*  p_y     = (float*)symaddr(g_y);
    __half* p_opre  = (__half*)symaddr(g_opre);
    float*  p_stfb  = (float*)symaddr(g_stfb);

    static cudaStream_t sA = nullptr, sB = nullptr;
    static cudaEvent_t eF = nullptr, eW = nullptr, eL = nullptr,
                       eWG = nullptr, eP = nullptr, eG = nullptr, eB = nullptr;
    if (!sA) {
        cudaStreamCreateWithFlags(&sA, cudaStreamNonBlocking);
        cudaStreamCreateWithFlags(&sB, cudaStreamNonBlocking);
        cudaEventCreateWithFlags(&eF, cudaEventDisableTiming);
        cudaEventCreateWithFlags(&eW, cudaEventDisableTiming);
        cudaEventCreateWithFlags(&eL, cudaEventDisableTiming);
        cudaEventCreateWithFlags(&eWG, cudaEventDisableTiming);
        cudaEventCreateWithFlags(&eP, cudaEventDisableTiming);
        cudaEventCreateWithFlags(&eG, cudaEventDisableTiming);
        cudaEventCreateWithFlags(&eB, cudaEventDisableTiming);
        cudaFuncSetAttribute(gemm_h<0>, cudaFuncAttributeMaxDynamicSharedMemorySize, GSMEM);
        cudaFuncSetAttribute(gemm_h<1>, cudaFuncAttributeMaxDynamicSharedMemorySize, GSMEM);
        cudaFuncSetAttribute(gemm_h<2>, cudaFuncAttributeMaxDynamicSharedMemorySize, GSMEM);
        cudaFuncSetAttribute(gemm_h<3>, cudaFuncAttributeMaxDynamicSharedMemorySize, GSMEM);
    }

    // ---- forks: packs run off the critical path
    cudaEventRecord(eF, 0);
    cudaStreamWaitEvent(sA, eF, 0);
    pack_w_kernel<<<(5 * 1024 * 1024) / 256, 256, 0, sA>>>(rW, kW, vW, gW, oW, p_W5);
    cudaEventRecord(eW, sA);
    cudaStreamWaitEvent(sB, eF, 0);
    pack_la_kernel<<<(384 * 1024) / 256, 256, 0, sB>>>(la[0], la[1], la[2], la[3], la[4], p_laP);
    pack_lb_kernel<<<(5 * 1024 * 64 + 5 * 1024 + 255) / 256, 256, 0, sB>>>(
        lb[0], lb[1], lb[2], lb[3], lb[4], p_lbP,
        ll[0], ll[1], ll[2], ll[3], ll[4], p_llP);
    cudaEventRecord(eB, sB);

    // ---- main chain
    premix_kernel<<<(int)(BTD / 1024), 256>>>(x, xw, p_dx, p_lerpx);

    // lora stage 1, split-K z=2
    cudaStreamWaitEvent(0, eB, 0);
    gemm_h<0><<<dim3(3, 32, 2), 256, GSMEM>>>(
        p_lerpx, 512, 1024, p_laP, 512, 1024, p_s1p, (long)BT * 384, 384,
        nullptr, 0, nullptr, nullptr, 512);
    combine_t1_kernel<<<(BT * 384) / 1024, 256>>>(p_s1p, p_t1);

    // fused lora stage 2 + mix: d-path slice (z=4) FIRST, so the sA chain
    // can start ~100us earlier and hide under the remaining work
    gemm_h<2><<<dim3(8, 32, 1), 256, GSMEM>>>(
        p_t1 + 4 * 64, 0, 384, p_lbP + 4 * 65536, 0, 64, p_in + 4 * BTD, 0, 1024,
        p_llP + 4 * 1024, 0, x, p_dx, 64);
    cudaEventRecord(eL, 0);

    // remaining 4 slices (r,k,v,g inputs)
    gemm_h<2><<<dim3(8, 32, 4), 256, GSMEM>>>(
        p_t1, 64, 384, p_lbP, 65536, 64, p_in, BTD, 1024,
        p_llP, 1024, x, p_dx, 64);

    // ---- fork: d-lora second pass (t2, w) on sA, parallel with mode2(z0-3) + rkv
    cudaStreamWaitEvent(sA, eL, 0);
    gemm_h<1><<<dim3(1, 32, 1), 256, GSMEM, sA>>>(
        p_in + 4 * BTD, 0, 1024, p_laP + 256 * 1024, 0, 1024, p_t2, 0, 128,
        nullptr, 0, nullptr, nullptr, 1024);
    gemm_h<3><<<dim3(8, 32, 1), 256, GSMEM, sA>>>(
        p_t2, 0, 128, p_lbP + 4 * 65536, 0, 64, p_w, 0, 1024,
        p_llP + 4 * 1024, 0, nullptr, nullptr, 64);
    cudaEventRecord(eWG, sA);

    // ---- r,k,v projections (need packed weights)
    cudaStreamWaitEvent(0, eW, 0);
    gemm_h<0><<<dim3(8, 32, 3), 256, GSMEM>>>(
        p_in, BTD, 1024, p_W5, 1024 * 1024, 1024, p_proj, BTD, 1024,
        nullptr, 0, nullptr, nullptr, 1024);

    // ---- fork: g projection on sB, parallel with the scan
    cudaEventRecord(eP, 0);
    cudaStreamWaitEvent(sB, eP, 0);
    gemm_h<0><<<dim3(8, 32, 1), 256, GSMEM, sB>>>(
        p_in + 3 * BTD, 0, 1024, p_W5 + 3ll * 1024 * 1024, 0, 1024,
        p_proj + 3 * BTD, 0, 1024, nullptr, 0, nullptr, nullptr, 1024);
    cudaEventRecord(eG, sB);

    // ---- recurrent scan (needs r,k,v + w)
    cudaStreamWaitEvent(0, eWG, 0);
    float* st_out = (out_size >= (int)(BTD + STATE)) ? (out + BTD) : p_stfb;
    scan3_kernel<<<2 * Bb * Hh, 256>>>(p_proj, p_w, p_proj + BTD, p_proj + 2 * BTD,
                                       init_state, u, p_y, st_out);

    // ---- gate (needs g) + output projection
    cudaStreamWaitEvent(0, eG, 0);
    gn_gate_kernel<<<(Bb * Tt * Hh) / 8, 256>>>(p_y, p_proj + 3 * BTD, ln_w, ln_b, p_opre);
    gemm_h<0><<<dim3(8, 32, 1), 256, GSMEM>>>(
        p_opre, 0, 1024, p_W5 + 4ll * 1024 * 1024, 0, 1024, out, 0, 1024,
        nullptr, 0, nullptr, nullptr, 1024);
}

// round 14
// speedup vs baseline: 1.4117x; 1.2106x over previous
#include <cuda_runtime.h>
#include <cuda_fp16.h>
#include <mma.h>
#include <math.h>

#define Bb 4
#define Tt 1024
#define Dd 1024
#define Hh 16
#define HDh 64
#define LR 64
#define BT (Bb*Tt)             /* 4096 */
#define BTD ((long)BT*Dd)      /* 4194304 */
#define STATE (Bb*Hh*HDh*HDh)  /* 262144 */

// ---------------- scratch (device globals; no allocation allowed) ----------
__device__ float  g_dx[BTD];
__device__ __half g_lerpx[BTD];
__device__ __half g_in[5*BTD];
__device__ __half g_t1[(long)BT*384];
__device__ float  g_s1p[2ll*BT*384];   // split-K partials for stage1
__device__ __half g_t2[(long)BT*128];
__device__ __half g_laP[384*1024];
__device__ __half g_lbP[5*1024*64];
__device__ float  g_llP[5*1024];
__device__ __half g_W5[5ll*1024*1024];
__device__ float  g_w[BTD];
__device__ float  g_proj[4*BTD];
__device__ float  g_y[BTD];
__device__ __half g_opre[BTD];
__device__ float  g_stfb[STATE];

__device__ __forceinline__ uint2 h4pack(float a, float b, float c, float d) {
    __half2 p0 = __floats2half2_rn(a, b);
    __half2 p1 = __floats2half2_rn(c, d);
    uint2 r;
    r.x = *reinterpret_cast<unsigned*>(&p0);
    r.y = *reinterpret_cast<unsigned*>(&p1);
    return r;
}

// ---------------- elementwise / pack kernels -------------------------------

// vectorized: 4 elements per thread
__global__ void __launch_bounds__(256) premix_kernel(
        const float* __restrict__ x, const float* __restrict__ xw,
        float* __restrict__ dx, __half* __restrict__ lerpx) {
    long idx = ((long)blockIdx.x * 256 + threadIdx.x) * 4;
    int dd = (int)(idx % Dd);
    long bt = idx / Dd;
    int t = (int)(bt % Tt);
    float4 xv = *(const float4*)&x[idx];
    float4 xp = make_float4(0.f, 0.f, 0.f, 0.f);
    if (t > 0) xp = *(const float4*)&x[idx - Dd];
    float4 wv = *(const float4*)&xw[dd];
    float4 d;
    d.x = xp.x - xv.x; d.y = xp.y - xv.y;
    d.z = xp.z - xv.z; d.w = xp.w - xv.w;
    *(float4*)&dx[idx] = d;
    uint2 o = h4pack(fmaf(d.x, wv.x, xv.x), fmaf(d.y, wv.y, xv.y),
                     fmaf(d.z, wv.z, xv.z), fmaf(d.w, wv.w, xv.w));
    *(uint2*)&lerpx[idx] = o;
}

__global__ void __launch_bounds__(256) pack_la_kernel(
        const float* __restrict__ a0, const float* __restrict__ a1,
        const float* __restrict__ a2, const float* __restrict__ a3,
        const float* __restrict__ a4, __half* __restrict__ dst) {
    long i = (long)blockIdx.x * 256 + threadIdx.x;
    int row = (int)(i >> 10);
    int col = (int)(i & 1023);
    int p = row >> 6;
    float v = 0.f;
    if (p < 5) {
        const float* src = (p == 0) ? a0 : (p == 1) ? a1 : (p == 2) ? a2
                         : (p == 3) ? a3 : a4;
        v = src[(long)(row & 63) * 1024 + col];
    }
    dst[i] = __float2half_rn(v);
}

__global__ void __launch_bounds__(256) pack_lb_kernel(
        const float* __restrict__ b0, const float* __restrict__ b1,
        const float* __restrict__ b2, const float* __restrict__ b3,
        const float* __restrict__ b4, __half* __restrict__ dstb,
        const float* __restrict__ l0, const float* __restrict__ l1,
        const float* __restrict__ l2, const float* __restrict__ l3,
        const float* __restrict__ l4, float* __restrict__ dstl) {
    long i = (long)blockIdx.x * 256 + threadIdx.x;   // 5*1024*64 + 5*1024
    if (i < 5ll * 1024 * 64) {
        int p = (int)(i >> 16);
        long r = i & 65535;
        const float* src = (p == 0) ? b0 : (p == 1) ? b1 : (p == 2) ? b2
                         : (p == 3) ? b3 : b4;
        dstb[i] = __float2half_rn(src[r]);
    } else {
        int j = (int)(i - 5ll * 1024 * 64);
        int p = j >> 10;
        int r = j & 1023;
        const float* src = (p == 0) ? l0 : (p == 1) ? l1 : (p == 2) ? l2
                         : (p == 3) ? l3 : l4;
        dstl[j] = src[r];
    }
}

__global__ void __launch_bounds__(256) pack_w_kernel(
        const float* __restrict__ w0, const float* __restrict__ w1,
        const float* __restrict__ w2, const float* __restrict__ w3,
        const float* __restrict__ w4, __half* __restrict__ dst) {
    long i = (long)blockIdx.x * 256 + threadIdx.x;
    int p = (int)(i >> 20);
    long r = i & 1048575;
    const float* src = (p == 0) ? w0 : (p == 1) ? w1 : (p == 2) ? w2
                     : (p == 3) ? w3 : w4;
    dst[i] = __float2half_rn(src[r]);
}

// t1 = half(tanh(p0 + p1))   (combine split-K partials)
__global__ void __launch_bounds__(256) combine_t1_kernel(
        const float* __restrict__ p, __half* __restrict__ dst) {
    long i = ((long)blockIdx.x * 256 + threadIdx.x) * 4;
    float4 a = *(const float4*)&p[i];
    float4 b = *(const float4*)&p[(long)BT * 384 + i];
    uint2 o = h4pack(tanhf(a.x + b.x), tanhf(a.y + b.y),
                     tanhf(a.z + b.z), tanhf(a.w + b.w));
    *(uint2*)&dst[i] = o;
}

// ---------------- fp16 tensor-core GEMM with fused epilogues ---------------
// PROVEN config: BKK=64, SLDH=72, 2-stage ping-pong, 2 CTAs/SM.
// MODE 0: Cf = acc                    (float out)
// MODE 1: Ch = half(tanh(acc))        (half out)
// MODE 2: Ch = half(x + dx*(acc+L))   (half out; x/dx row length 1024)
// MODE 3: Cf = exp(-exp(acc+L))       (float out)
#define BKK 64
#define SLDH 72
#define PIPEH (2*128*SLDH)
#define GSMEM (2*PIPEH*2)

template<int MODE>
__global__ void __launch_bounds__(256) gemm_h(
        const __half* __restrict__ A, long sAz, int lda,
        const __half* __restrict__ W, long sWz, int ldw,
        void* __restrict__ Cv, long sCz, int ldc,
        const float* __restrict__ L, long sLz,
        const float* __restrict__ x, const float* __restrict__ dx,
        int K) {
    using namespace nvcuda;
    extern __shared__ __half sm[];
    const int tid = threadIdx.x;
    const int z = blockIdx.z;
    A += (long)z * sAz;
    W += (long)z * sWz;
    if (MODE >= 2) L += (long)z * sLz;
    float* Cf = (float*)Cv + (long)z * sCz;
    __half* Ch = (__half*)Cv + (long)z * sCz;
    const int bm = blockIdx.y * 128;
    const int bn = blockIdx.x * 128;
    const int r = tid >> 3;
    const int q = (tid & 7) * 8;
    const __half* aP = A + (long)(bm + r) * lda + q;
    const __half* wP = W + (long)(bn + r) * ldw + q;
    unsigned dA = (unsigned)__cvta_generic_to_shared(sm) + (r * SLDH + q) * 2;
    const int wid = tid >> 5;
    const int wy = wid >> 1;
    const int wx = wid & 1;

    wmma::fragment<wmma::accumulator, 16, 16, 16, float> acc[2][4];
    #pragma unroll
    for (int i = 0; i < 2; i++)
        #pragma unroll
        for (int j = 0; j < 4; j++)
            wmma::fill_fragment(acc[i][j], 0.0f);

#define ISSUE(st, k0) do {                                                   \
        unsigned _a = dA + (st) * (PIPEH * 2);                               \
        unsigned _b = _a + 128 * SLDH * 2;                                   \
        _Pragma("unroll")                                                    \
        for (int _i = 0; _i < 4; _i++) {                                     \
            asm volatile("cp.async.cg.shared.global [%0], [%1], 16;\n" ::    \
                "r"(_a + _i * 32 * SLDH * 2),                                \
                "l"(aP + (long)_i * 32 * lda + (k0)));                       \
            asm volatile("cp.async.cg.shared.global [%0], [%1], 16;\n" ::    \
                "r"(_b + _i * 32 * SLDH * 2),                                \
                "l"(wP + (long)_i * 32 * ldw + (k0)));                       \
        }                                                                    \
        asm volatile("cp.async.commit_group;\n");                            \
    } while (0)

    const int nIter = K / BKK;
    ISSUE(0, 0);
    if (nIter > 1) {
        ISSUE(1, BKK);
        asm volatile("cp.async.wait_group 1;\n");
    } else {
        asm volatile("cp.async.wait_group 0;\n");
    }
    __syncthreads();

    for (int it = 0; it < nIter; it++) {
        int s = it & 1;
        const __half* sA = sm + s * PIPEH;
        const __half* sB = sA + 128 * SLDH;
        #pragma unroll
        for (int kk = 0; kk < BKK; kk += 16) {
            wmma::fragment<wmma::matrix_a, 16, 16, 16, __half, wmma::row_major> af[2];
            wmma::fragment<wmma::matrix_b, 16, 16, 16, __half, wmma::col_major> bf[4];
            #pragma unroll
            for (int i = 0; i < 2; i++)
                wmma::load_matrix_sync(af[i], sA + (wy * 32 + i * 16) * SLDH + kk, SLDH);
            #pragma unroll
            for (int j = 0; j < 4; j++)
                wmma::load_matrix_sync(bf[j], sB + (wx * 64 + j * 16) * SLDH + kk, SLDH);
            #pragma unroll
            for (int i = 0; i < 2; i++)
                #pragma unroll
                for (int j = 0; j < 4; j++)
                    wmma::mma_sync(acc[i][j], af[i], bf[j], acc[i][j]);
        }
        __syncthreads();
        if (it + 2 < nIter) {
            ISSUE(s, (it + 2) * BKK);
            asm volatile("cp.async.wait_group 1;\n");
            __syncthreads();
        } else if (it + 1 < nIter) {
            asm volatile("cp.async.wait_group 0;\n");
            __syncthreads();
        }
    }
#undef ISSUE

    if (MODE == 0) {
        #pragma unroll
        for (int i = 0; i < 2; i++)
            #pragma unroll
            for (int j = 0; j < 4; j++)
                wmma::store_matrix_sync(
                    Cf + (long)(bm + wy * 32 + i * 16) * ldc + bn + wx * 64 + j * 16,
                    acc[i][j], ldc, wmma::mem_row_major);
    } else {
        float* smf = reinterpret_cast<float*>(sm);
        __syncthreads();
        #pragma unroll
        for (int i = 0; i < 2; i++)
            #pragma unroll
            for (int j = 0; j < 4; j++)
                wmma::store_matrix_sync(
                    smf + (wy * 32 + i * 16) * 128 + wx * 64 + j * 16,
                    acc[i][j], 128, wmma::mem_row_major);
        __syncthreads();
        int row = tid >> 1;
        int c0 = (tid & 1) * 64;
        long gro = bm + row;
        #pragma unroll
        for (int i = 0; i < 16; i++) {
            int c = c0 + i * 4;
            float4 m = *(float4*)&smf[row * 128 + c];
            if (MODE == 1) {
                uint2 o = h4pack(tanhf(m.x), tanhf(m.y), tanhf(m.z), tanhf(m.w));
                *(uint2*)&Ch[gro * ldc + bn + c] = o;
            } else if (MODE == 2) {
                float4 lv = *(const float4*)&L[bn + c];
                long gi = gro * 1024 + bn + c;
                float4 xv = *(const float4*)&x[gi];
                float4 dv = *(const float4*)&dx[gi];
                uint2 o = h4pack(fmaf(dv.x, m.x + lv.x, xv.x),
                                 fmaf(dv.y, m.y + lv.y, xv.y),
                                 fmaf(dv.z, m.z + lv.z, xv.z),
                                 fmaf(dv.w, m.w + lv.w, xv.w));
                *(uint2*)&Ch[gro * ldc + bn + c] = o;
            } else {
                float4 lv = *(const float4*)&L[bn + c];
                float4 o;
                o.x = expf(-expf(m.x + lv.x));
                o.y = expf(-expf(m.y + lv.y));
                o.z = expf(-expf(m.z + lv.z));
                o.w = expf(-expf(m.w + lv.w));
                *(float4*)&Cf[gro * ldc + bn + c] = o;
            }
        }
    }
}

// ---------------- recurrent scan: 128 CTAs, ONE sync per TWO timesteps -----
// 4 rotating smem buffers; iteration it reads pair (it&1)*2+{0,1}, writes the
// other pair. All cross-warp hazards cross exactly one barrier.
__global__ void __launch_bounds__(256) scan4_kernel(
        const float* __restrict__ r, const float* __restrict__ w,
        const float* __restrict__ k, const float* __restrict__ v,
        const float* __restrict__ init_state, const float* __restrict__ u,
        float* __restrict__ y, float* __restrict__ state_out) {
    int cta = blockIdx.x;
    int bh = cta >> 1, jh = cta & 1;
    int b = bh / Hh, h = bh % Hh;
    int tid = threadIdx.x;
    int j32 = tid & 31;
    int gi = tid >> 5;
    int j = jh * 32 + j32;
    __shared__ float sh[4][224];
    __shared__ float ypart[4][8][32];
    float S[8], uu[8];
    #pragma unroll
    for (int ii = 0; ii < 8; ii++) {
        int i = gi * 8 + ii;
        S[ii] = init_state[(long)(h * 64 + i) * 64 + j];
        uu[ii] = u[h * 64 + i];
    }
    long base = (long)b * Tt * Dd + (long)h * 64;
    const float* myp = nullptr;
    if (tid < 64)       myp = r + base + tid;
    else if (tid < 128) myp = w + base + (tid - 64);
    else if (tid < 192) myp = k + base + (tid - 128);
    else if (tid < 224) myp = v + base + jh * 32 + (tid - 192);

    // prologue: stage t=0,1; prefetch t=2,3 (Tt >= 4)
    if (tid < 224) {
        sh[0][tid] = myp[0];
        sh[1][tid] = myp[Dd];
    }
    __syncthreads();
    float p0 = 0.f, p1 = 0.f;
    if (tid < 224) {
        p0 = myp[2l * Dd];
        p1 = myp[3l * Dd];
    }

    for (int it = 0; it < Tt / 2; it++) {
        int t = it * 2;
        int rb = (it & 1) * 2;          // read buffer pair
        int wb = rb ^ 2;                // write buffer pair
        // timestep t
        {
            const float* s0 = sh[rb];
            float vj = s0[192 + j32];
            float acc = 0.f;
            #pragma unroll
            for (int ii = 0; ii < 8; ii++) {
                int i = gi * 8 + ii;
                float kv = s0[128 + i] * vj;
                acc = fmaf(s0[i], fmaf(uu[ii], kv, S[ii]), acc);
                S[ii] = fmaf(s0[64 + i], S[ii], kv);
            }
            ypart[rb][gi][j32] = acc;
        }
        // timestep t+1
        {
            const float* s1 = sh[rb + 1];
            float vj = s1[192 + j32];
            float acc = 0.f;
            #pragma unroll
            for (int ii = 0; ii < 8; ii++) {
                int i = gi * 8 + ii;
                float kv = s1[128 + i] * vj;
                acc = fmaf(s1[i], fmaf(uu[ii], kv, S[ii]), acc);
                S[ii] = fmaf(s1[64 + i], S[ii], kv);
            }
            ypart[rb + 1][gi][j32] = acc;
        }
        if (tid < 224) {
            sh[wb][tid] = p0;
            sh[wb + 1][tid] = p1;
            int tn = t + 4;
            if (tn < Tt) {
                p0 = myp[(long)tn * Dd];
                p1 = myp[(long)(tn + 1) * Dd];
            }
        }
        __syncthreads();
        if (gi == 0) {
            float y0 = 0.f, y1 = 0.f;
            #pragma unroll
            for (int g2 = 0; g2 < 8; g2++) {
                y0 += ypart[rb][g2][j32];
                y1 += ypart[rb + 1][g2][j32];
            }
            y[base + (long)t * Dd + j] = y0;
            y[base + (long)(t + 1) * Dd + j] = y1;
        }
    }
    #pragma unroll
    for (int ii = 0; ii < 8; ii++) {
        int i = gi * 8 + ii;
        state_out[(long)((b * Hh + h) * 64 + i) * 64 + j] = S[ii];
    }
}

// ---------------- groupnorm + silu gate ------------------------------------
__global__ void __launch_bounds__(256) gn_gate_kernel(
        const float* __restrict__ y, const float* __restrict__ g,
        const float* __restrict__ lnw, const float* __restrict__ lnb,
        __half* __restrict__ out) {
    long warp = ((long)blockIdx.x * blockDim.x + threadIdx.x) >> 5;
    int lane = threadIdx.x & 31;
    if (warp >= (long)Bb * Tt * Hh) return;
    const float* yp = y + warp * 64;
    float v0 = yp[lane], v1 = yp[lane + 32];
    float s = v0 + v1;
    #pragma unroll
    for (int off = 16; off > 0; off >>= 1) s += __shfl_xor_sync(0xffffffffu, s, off);
    float mean = s * (1.f / 64.f);
    float d0 = v0 - mean, d1 = v1 - mean;
    float vs = d0 * d0 + d1 * d1;
    #pragma unroll
    for (int off = 16; off > 0; off >>= 1) vs += __shfl_xor_sync(0xffffffffu, vs, off);
    float inv = rsqrtf(vs * (1.f / 64.f) + 1e-5f);
    float n0 = fmaf(d0 * inv, lnw[lane], lnb[lane]);
    float n1 = fmaf(d1 * inv, lnw[lane + 32], lnb[lane + 32]);
    float g0 = g[warp * 64 + lane];
    float g1 = g[warp * 64 + lane + 32];
    float s0 = g0 / (1.f + expf(-g0));
    float s1 = g1 / (1.f + expf(-g1));
    out[warp * 64 + lane] = __float2half_rn(s0 * n0);
    out[warp * 64 + lane + 32] = __float2half_rn(s1 * n1);
}

// ---------------- host -----------------------------------------------------
static void* symaddr(const void* s) {
    void* p = nullptr;
    cudaGetSymbolAddress(&p, s);
    return p;
}

extern "C" void kernel_launch(void* const* d_in, const int* in_sizes, int n_in,
                              void* d_out, int out_size) {
    (void)in_sizes; (void)n_in;
    const float* x    = (const float*)d_in[0];
    const float* xw   = (const float*)d_in[1];
    const float* rW   = (const float*)d_in[2];
    const float* kW   = (const float*)d_in[3];
    const float* vW   = (const float*)d_in[4];
    const float* gW   = (const float*)d_in[5];
    const float* la[5] = {(const float*)d_in[6],  (const float*)d_in[9],
                          (const float*)d_in[12], (const float*)d_in[15],
                          (const float*)d_in[18]};
    const float* lb[5] = {(const float*)d_in[7],  (const float*)d_in[10],
                          (const float*)d_in[13], (const float*)d_in[16],
                          (const float*)d_in[19]};
    const float* ll[5] = {(const float*)d_in[8],  (const float*)d_in[11],
                          (const float*)d_in[14], (const float*)d_in[17],
                          (const float*)d_in[20]};
    const float* ln_w = (const float*)d_in[21];
    const float* ln_b = (const float*)d_in[22];
    const float* oW   = (const float*)d_in[23];
    const float* init_state = (const float*)d_in[24];
    const float* u    = (const float*)d_in[25];

    float* out = (float*)d_out;

    float*  p_dx    = (float*)symaddr(g_dx);
    __half* p_lerpx = (__half*)symaddr(g_lerpx);
    __half* p_in    = (__half*)symaddr(g_in);
    __half* p_t1    = (__half*)symaddr(g_t1);
    float*  p_s1p   = (float*)symaddr(g_s1p);
    __half* p_t2    = (__half*)symaddr(g_t2);
    __half* p_laP   = (__half*)symaddr(g_laP);
    __half* p_lbP   = (__half*)symaddr(g_lbP);
    float*  p_llP   = (float*)symaddr(g_llP);
    __half* p_W5    = (__half*)symaddr(g_W5);
    float*  p_w     = (float*)symaddr(g_w);
    float*  p_proj  = (float*)symaddr(g_proj);
    float*  p_y     = (float*)symaddr(g_y);
    __half* p_opre  = (__half*)symaddr(g_opre);
    float*  p_stfb  = (float*)symaddr(g_stfb);

    static cudaStream_t sA = nullptr, sB = nullptr;
    static cudaEvent_t eF = nullptr, eW = nullptr, eL = nullptr,
                       eWG = nullptr, eP = nullptr, eG = nullptr, eB = nullptr;
    if (!sA) {
        cudaStreamCreateWithFlags(&sA, cudaStreamNonBlocking);
        cudaStreamCreateWithFlags(&sB, cudaStreamNonBlocking);
        cudaEventCreateWithFlags(&eF, cudaEventDisableTiming);
        cudaEventCreateWithFlags(&eW, cudaEventDisableTiming);
        cudaEventCreateWithFlags(&eL, cudaEventDisableTiming);
        cudaEventCreateWithFlags(&eWG, cudaEventDisableTiming);
        cudaEventCreateWithFlags(&eP, cudaEventDisableTiming);
        cudaEventCreateWithFlags(&eG, cudaEventDisableTiming);
        cudaEventCreateWithFlags(&eB, cudaEventDisableTiming);
        cudaFuncSetAttribute(gemm_h<0>, cudaFuncAttributeMaxDynamicSharedMemorySize, GSMEM);
        cudaFuncSetAttribute(gemm_h<1>, cudaFuncAttributeMaxDynamicSharedMemorySize, GSMEM);
        cudaFuncSetAttribute(gemm_h<2>, cudaFuncAttributeMaxDynamicSharedMemorySize, GSMEM);
        cudaFuncSetAttribute(gemm_h<3>, cudaFuncAttributeMaxDynamicSharedMemorySize, GSMEM);
    }

    // ---- forks: packs run off the critical path
    cudaEventRecord(eF, 0);
    cudaStreamWaitEvent(sA, eF, 0);
    pack_w_kernel<<<(5 * 1024 * 1024) / 256, 256, 0, sA>>>(rW, kW, vW, gW, oW, p_W5);
    cudaEventRecord(eW, sA);
    cudaStreamWaitEvent(sB, eF, 0);
    pack_la_kernel<<<(384 * 1024) / 256, 256, 0, sB>>>(la[0], la[1], la[2], la[3], la[4], p_laP);
    pack_lb_kernel<<<(5 * 1024 * 64 + 5 * 1024 + 255) / 256, 256, 0, sB>>>(
        lb[0], lb[1], lb[2], lb[3], lb[4], p_lbP,
        ll[0], ll[1], ll[2], ll[3], ll[4], p_llP);
    cudaEventRecord(eB, sB);

    // ---- main chain
    premix_kernel<<<(int)(BTD / 1024), 256>>>(x, xw, p_dx, p_lerpx);

    // lora stage 1, split-K z=2
    cudaStreamWaitEvent(0, eB, 0);
    gemm_h<0><<<dim3(3, 32, 2), 256, GSMEM>>>(
        p_lerpx, 512, 1024, p_laP, 512, 1024, p_s1p, (long)BT * 384, 384,
        nullptr, 0, nullptr, nullptr, 512);
    combine_t1_kernel<<<(BT * 384) / 1024, 256>>>(p_s1p, p_t1);

    // fused lora stage 2 + mix: d-path slice (z=4) FIRST
    gemm_h<2><<<dim3(8, 32, 1), 256, GSMEM>>>(
        p_t1 + 4 * 64, 0, 384, p_lbP + 4 * 65536, 0, 64, p_in + 4 * BTD, 0, 1024,
        p_llP + 4 * 1024, 0, x, p_dx, 64);
    cudaEventRecord(eL, 0);

    // remaining 4 slices (r,k,v,g inputs)
    gemm_h<2><<<dim3(8, 32, 4), 256, GSMEM>>>(
        p_t1, 64, 384, p_lbP, 65536, 64, p_in, BTD, 1024,
        p_llP, 1024, x, p_dx, 64);

    // ---- fork: d-lora second pass (t2, w) on sA
    cudaStreamWaitEvent(sA, eL, 0);
    gemm_h<1><<<dim3(1, 32, 1), 256, GSMEM, sA>>>(
        p_in + 4 * BTD, 0, 1024, p_laP + 256 * 1024, 0, 1024, p_t2, 0, 128,
        nullptr, 0, nullptr, nullptr, 1024);
    gemm_h<3><<<dim3(8, 32, 1), 256, GSMEM, sA>>>(
        p_t2, 0, 128, p_lbP + 4 * 65536, 0, 64, p_w, 0, 1024,
        p_llP + 4 * 1024, 0, nullptr, nullptr, 64);
    cudaEventRecord(eWG, sA);

    // ---- r,k,v projections (need packed weights)
    cudaStreamWaitEvent(0, eW, 0);
    gemm_h<0><<<dim3(8, 32, 3), 256, GSMEM>>>(
        p_in, BTD, 1024, p_W5, 1024 * 1024, 1024, p_proj, BTD, 1024,
        nullptr, 0, nullptr, nullptr, 1024);

    // ---- fork: g projection on sB, parallel with the scan
    cudaEventRecord(eP, 0);
    cudaStreamWaitEvent(sB, eP, 0);
    gemm_h<0><<<dim3(8, 32, 1), 256, GSMEM, sB>>>(
        p_in + 3 * BTD, 0, 1024, p_W5 + 3ll * 1024 * 1024, 0, 1024,
        p_proj + 3 * BTD, 0, 1024, nullptr, 0, nullptr, nullptr, 1024);
    cudaEventRecord(eG, sB);

    // ---- recurrent scan (needs r,k,v + w)
    cudaStreamWaitEvent(0, eWG, 0);
    float* st_out = (out_size >= (int)(BTD + STATE)) ? (out + BTD) : p_stfb;
    scan4_kernel<<<2 * Bb * Hh, 256>>>(p_proj, p_w, p_proj + BTD, p_proj + 2 * BTD,
                                       init_state, u, p_y, st_out);

    // ---- gate (needs g) + output projection
    cudaStreamWaitEvent(0, eG, 0);
    gn_gate_kernel<<<(Bb * Tt * Hh) / 8, 256>>>(p_y, p_proj + 3 * BTD, ln_w, ln_b, p_opre);
    gemm_h<0><<<dim3(8, 32, 1), 256, GSMEM>>>(
        p_opre, 0, 1024, p_W5 + 4ll * 1024 * 1024, 0, 1024, out, 0, 1024,
        nullptr, 0, nullptr, nullptr, 1024);
}

// round 15
// speedup vs baseline: 1.7556x; 1.2436x over previous
#include <cuda_runtime.h>
#include <cuda_fp16.h>
#include <mma.h>
#include <math.h>

#define Bb 4
#define Tt 1024
#define Dd 1024
#define Hh 16
#define HDh 64
#define LR 64
#define BT (Bb*Tt)             /* 4096 */
#define BTD ((long)BT*Dd)      /* 4194304 */
#define STATE (Bb*Hh*HDh*HDh)  /* 262144 */

// ---------------- scratch (device globals; no allocation allowed) ----------
__device__ float  g_dx[BTD];
__device__ __half g_lerpx[BTD];
__device__ __half g_in[5*BTD];
__device__ __half g_t1[(long)BT*384];
__device__ float  g_s1p[2ll*BT*384];   // split-K partials for stage1
__device__ __half g_t2[(long)BT*128];
__device__ __half g_laP[384*1024];
__device__ __half g_lbP[5*1024*64];
__device__ float  g_llP[5*1024];
__device__ __half g_W5[5ll*1024*1024];
__device__ float  g_w[BTD];
__device__ float  g_proj[4*BTD];
__device__ float  g_y[BTD];
__device__ __half g_opre[BTD];
__device__ float  g_stfb[STATE];

__device__ __forceinline__ uint2 h4pack(float a, float b, float c, float d) {
    __half2 p0 = __floats2half2_rn(a, b);
    __half2 p1 = __floats2half2_rn(c, d);
    uint2 r;
    r.x = *reinterpret_cast<unsigned*>(&p0);
    r.y = *reinterpret_cast<unsigned*>(&p1);
    return r;
}

// ---------------- elementwise / pack kernels -------------------------------

__global__ void __launch_bounds__(256) premix_kernel(
        const float* __restrict__ x, const float* __restrict__ xw,
        float* __restrict__ dx, __half* __restrict__ lerpx) {
    long idx = ((long)blockIdx.x * 256 + threadIdx.x) * 4;
    int dd = (int)(idx % Dd);
    long bt = idx / Dd;
    int t = (int)(bt % Tt);
    float4 xv = *(const float4*)&x[idx];
    float4 xp = make_float4(0.f, 0.f, 0.f, 0.f);
    if (t > 0) xp = *(const float4*)&x[idx - Dd];
    float4 wv = *(const float4*)&xw[dd];
    float4 d;
    d.x = xp.x - xv.x; d.y = xp.y - xv.y;
    d.z = xp.z - xv.z; d.w = xp.w - xv.w;
    *(float4*)&dx[idx] = d;
    uint2 o = h4pack(fmaf(d.x, wv.x, xv.x), fmaf(d.y, wv.y, xv.y),
                     fmaf(d.z, wv.z, xv.z), fmaf(d.w, wv.w, xv.w));
    *(uint2*)&lerpx[idx] = o;
}

__global__ void __launch_bounds__(256) pack_la_kernel(
        const float* __restrict__ a0, const float* __restrict__ a1,
        const float* __restrict__ a2, const float* __restrict__ a3,
        const float* __restrict__ a4, __half* __restrict__ dst) {
    long i = (long)blockIdx.x * 256 + threadIdx.x;
    int row = (int)(i >> 10);
    int col = (int)(i & 1023);
    int p = row >> 6;
    float v = 0.f;
    if (p < 5) {
        const float* src = (p == 0) ? a0 : (p == 1) ? a1 : (p == 2) ? a2
                         : (p == 3) ? a3 : a4;
        v = src[(long)(row & 63) * 1024 + col];
    }
    dst[i] = __float2half_rn(v);
}

__global__ void __launch_bounds__(256) pack_lb_kernel(
        const float* __restrict__ b0, const float* __restrict__ b1,
        const float* __restrict__ b2, const float* __restrict__ b3,
        const float* __restrict__ b4, __half* __restrict__ dstb,
        const float* __restrict__ l0, const float* __restrict__ l1,
        const float* __restrict__ l2, const float* __restrict__ l3,
        const float* __restrict__ l4, float* __restrict__ dstl) {
    long i = (long)blockIdx.x * 256 + threadIdx.x;
    if (i < 5ll * 1024 * 64) {
        int p = (int)(i >> 16);
        long r = i & 65535;
        const float* src = (p == 0) ? b0 : (p == 1) ? b1 : (p == 2) ? b2
                         : (p == 3) ? b3 : b4;
        dstb[i] = __float2half_rn(src[r]);
    } else {
        int j = (int)(i - 5ll * 1024 * 64);
        int p = j >> 10;
        int r = j & 1023;
        const float* src = (p == 0) ? l0 : (p == 1) ? l1 : (p == 2) ? l2
                         : (p == 3) ? l3 : l4;
        dstl[j] = src[r];
    }
}

__global__ void __launch_bounds__(256) pack_w_kernel(
        const float* __restrict__ w0, const float* __restrict__ w1,
        const float* __restrict__ w2, const float* __restrict__ w3,
        const float* __restrict__ w4, __half* __restrict__ dst) {
    long i = (long)blockIdx.x * 256 + threadIdx.x;
    int p = (int)(i >> 20);
    long r = i & 1048575;
    const float* src = (p == 0) ? w0 : (p == 1) ? w1 : (p == 2) ? w2
                     : (p == 3) ? w3 : w4;
    dst[i] = __float2half_rn(src[r]);
}

__global__ void __launch_bounds__(256) combine_t1_kernel(
        const float* __restrict__ p, __half* __restrict__ dst) {
    long i = ((long)blockIdx.x * 256 + threadIdx.x) * 4;
    float4 a = *(const float4*)&p[i];
    float4 b = *(const float4*)&p[(long)BT * 384 + i];
    uint2 o = h4pack(tanhf(a.x + b.x), tanhf(a.y + b.y),
                     tanhf(a.z + b.z), tanhf(a.w + b.w));
    *(uint2*)&dst[i] = o;
}

// ---------------- fp16 tensor-core GEMM with fused epilogues ---------------
// PROVEN config: BKK=64, SLDH=72, 2-stage ping-pong, 2 CTAs/SM.
#define BKK 64
#define SLDH 72
#define PIPEH (2*128*SLDH)
#define GSMEM (2*PIPEH*2)

template<int MODE>
__global__ void __launch_bounds__(256) gemm_h(
        const __half* __restrict__ A, long sAz, int lda,
        const __half* __restrict__ W, long sWz, int ldw,
        void* __restrict__ Cv, long sCz, int ldc,
        const float* __restrict__ L, long sLz,
        const float* __restrict__ x, const float* __restrict__ dx,
        int K) {
    using namespace nvcuda;
    extern __shared__ __half sm[];
    const int tid = threadIdx.x;
    const int z = blockIdx.z;
    A += (long)z * sAz;
    W += (long)z * sWz;
    if (MODE >= 2) L += (long)z * sLz;
    float* Cf = (float*)Cv + (long)z * sCz;
    __half* Ch = (__half*)Cv + (long)z * sCz;
    const int bm = blockIdx.y * 128;
    const int bn = blockIdx.x * 128;
    const int r = tid >> 3;
    const int q = (tid & 7) * 8;
    const __half* aP = A + (long)(bm + r) * lda + q;
    const __half* wP = W + (long)(bn + r) * ldw + q;
    unsigned dA = (unsigned)__cvta_generic_to_shared(sm) + (r * SLDH + q) * 2;
    const int wid = tid >> 5;
    const int wy = wid >> 1;
    const int wx = wid & 1;

    wmma::fragment<wmma::accumulator, 16, 16, 16, float> acc[2][4];
    #pragma unroll
    for (int i = 0; i < 2; i++)
        #pragma unroll
        for (int j = 0; j < 4; j++)
            wmma::fill_fragment(acc[i][j], 0.0f);

#define ISSUE(st, k0) do {                                                   \
        unsigned _a = dA + (st) * (PIPEH * 2);                               \
        unsigned _b = _a + 128 * SLDH * 2;                                   \
        _Pragma("unroll")                                                    \
        for (int _i = 0; _i < 4; _i++) {                                     \
            asm volatile("cp.async.cg.shared.global [%0], [%1], 16;\n" ::    \
                "r"(_a + _i * 32 * SLDH * 2),                                \
                "l"(aP + (long)_i * 32 * lda + (k0)));                       \
            asm volatile("cp.async.cg.shared.global [%0], [%1], 16;\n" ::    \
                "r"(_b + _i * 32 * SLDH * 2),                                \
                "l"(wP + (long)_i * 32 * ldw + (k0)));                       \
        }                                                                    \
        asm volatile("cp.async.commit_group;\n");                            \
    } while (0)

    const int nIter = K / BKK;
    ISSUE(0, 0);
    if (nIter > 1) {
        ISSUE(1, BKK);
        asm volatile("cp.async.wait_group 1;\n");
    } else {
        asm volatile("cp.async.wait_group 0;\n");
    }
    __syncthreads();

    for (int it = 0; it < nIter; it++) {
        int s = it & 1;
        const __half* sA = sm + s * PIPEH;
        const __half* sB = sA + 128 * SLDH;
        #pragma unroll
        for (int kk = 0; kk < BKK; kk += 16) {
            wmma::fragment<wmma::matrix_a, 16, 16, 16, __half, wmma::row_major> af[2];
            wmma::fragment<wmma::matrix_b, 16, 16, 16, __half, wmma::col_major> bf[4];
            #pragma unroll
            for (int i = 0; i < 2; i++)
                wmma::load_matrix_sync(af[i], sA + (wy * 32 + i * 16) * SLDH + kk, SLDH);
            #pragma unroll
            for (int j = 0; j < 4; j++)
                wmma::load_matrix_sync(bf[j], sB + (wx * 64 + j * 16) * SLDH + kk, SLDH);
            #pragma unroll
            for (int i = 0; i < 2; i++)
                #pragma unroll
                for (int j = 0; j < 4; j++)
                    wmma::mma_sync(acc[i][j], af[i], bf[j], acc[i][j]);
        }
        __syncthreads();
        if (it + 2 < nIter) {
            ISSUE(s, (it + 2) * BKK);
            asm volatile("cp.async.wait_group 1;\n");
            __syncthreads();
        } else if (it + 1 < nIter) {
            asm volatile("cp.async.wait_group 0;\n");
            __syncthreads();
        }
    }
#undef ISSUE

    if (MODE == 0) {
        #pragma unroll
        for (int i = 0; i < 2; i++)
            #pragma unroll
            for (int j = 0; j < 4; j++)
                wmma::store_matrix_sync(
                    Cf + (long)(bm + wy * 32 + i * 16) * ldc + bn + wx * 64 + j * 16,
                    acc[i][j], ldc, wmma::mem_row_major);
    } else {
        float* smf = reinterpret_cast<float*>(sm);
        __syncthreads();
        #pragma unroll
        for (int i = 0; i < 2; i++)
            #pragma unroll
            for (int j = 0; j < 4; j++)
                wmma::store_matrix_sync(
                    smf + (wy * 32 + i * 16) * 128 + wx * 64 + j * 16,
                    acc[i][j], 128, wmma::mem_row_major);
        __syncthreads();
        int row = tid >> 1;
        int c0 = (tid & 1) * 64;
        long gro = bm + row;
        #pragma unroll
        for (int i = 0; i < 16; i++) {
            int c = c0 + i * 4;
            float4 m = *(float4*)&smf[row * 128 + c];
            if (MODE == 1) {
                uint2 o = h4pack(tanhf(m.x), tanhf(m.y), tanhf(m.z), tanhf(m.w));
                *(uint2*)&Ch[gro * ldc + bn + c] = o;
            } else if (MODE == 2) {
                float4 lv = *(const float4*)&L[bn + c];
                long gi = gro * 1024 + bn + c;
                float4 xv = *(const float4*)&x[gi];
                float4 dv = *(const float4*)&dx[gi];
                uint2 o = h4pack(fmaf(dv.x, m.x + lv.x, xv.x),
                                 fmaf(dv.y, m.y + lv.y, xv.y),
                                 fmaf(dv.z, m.z + lv.z, xv.z),
                                 fmaf(dv.w, m.w + lv.w, xv.w));
                *(uint2*)&Ch[gro * ldc + bn + c] = o;
            } else {
                float4 lv = *(const float4*)&L[bn + c];
                float4 o;
                o.x = expf(-expf(m.x + lv.x));
                o.y = expf(-expf(m.y + lv.y));
                o.z = expf(-expf(m.z + lv.z));
                o.w = expf(-expf(m.w + lv.w));
                *(float4*)&Cf[gro * ldc + bn + c] = o;
            }
        }
    }
}

// ---------------- recurrent scan: 128 CTAs, ONE sync per FOUR timesteps ----
// 8 rotating smem buffers; iteration it reads quad (it&1)*4+{0..3}, writes the
// other quad. All cross-warp hazards cross exactly one barrier.
__global__ void __launch_bounds__(256) scan8_kernel(
        const float* __restrict__ r, const float* __restrict__ w,
        const float* __restrict__ k, const float* __restrict__ v,
        const float* __restrict__ init_state, const float* __restrict__ u,
        float* __restrict__ y, float* __restrict__ state_out) {
    int cta = blockIdx.x;
    int bh = cta >> 1, jh = cta & 1;
    int b = bh / Hh, h = bh % Hh;
    int tid = threadIdx.x;
    int j32 = tid & 31;
    int gi = tid >> 5;
    int j = jh * 32 + j32;
    __shared__ float sh[8][224];
    __shared__ float ypart[8][8][32];
    float S[8], uu[8];
    #pragma unroll
    for (int ii = 0; ii < 8; ii++) {
        int i = gi * 8 + ii;
        S[ii] = init_state[(long)(h * 64 + i) * 64 + j];
        uu[ii] = u[h * 64 + i];
    }
    long base = (long)b * Tt * Dd + (long)h * 64;
    const float* myp = nullptr;
    if (tid < 64)       myp = r + base + tid;
    else if (tid < 128) myp = w + base + (tid - 64);
    else if (tid < 192) myp = k + base + (tid - 128);
    else if (tid < 224) myp = v + base + jh * 32 + (tid - 192);

    // prologue: stage t=0..3; prefetch t=4..7 (Tt >= 8)
    if (tid < 224) {
        sh[0][tid] = myp[0];
        sh[1][tid] = myp[Dd];
        sh[2][tid] = myp[2l * Dd];
        sh[3][tid] = myp[3l * Dd];
    }
    __syncthreads();
    float p0 = 0.f, p1 = 0.f, p2 = 0.f, p3 = 0.f;
    if (tid < 224) {
        p0 = myp[4l * Dd];
        p1 = myp[5l * Dd];
        p2 = myp[6l * Dd];
        p3 = myp[7l * Dd];
    }

    for (int it = 0; it < Tt / 4; it++) {
        int t = it * 4;
        int rb = (it & 1) * 4;          // read quad
        int wb = rb ^ 4;                // write quad
        #pragma unroll
        for (int st = 0; st < 4; st++) {
            const float* s0 = sh[rb + st];
            float vj = s0[192 + j32];
            float acc = 0.f;
            #pragma unroll
            for (int ii = 0; ii < 8; ii++) {
                int i = gi * 8 + ii;
                float kv = s0[128 + i] * vj;
                acc = fmaf(s0[i], fmaf(uu[ii], kv, S[ii]), acc);
                S[ii] = fmaf(s0[64 + i], S[ii], kv);
            }
            ypart[rb + st][gi][j32] = acc;
        }
        if (tid < 224) {
            sh[wb][tid] = p0;
            sh[wb + 1][tid] = p1;
            sh[wb + 2][tid] = p2;
            sh[wb + 3][tid] = p3;
            int tn = t + 8;
            if (tn < Tt) {
                p0 = myp[(long)tn * Dd];
                p1 = myp[(long)(tn + 1) * Dd];
                p2 = myp[(long)(tn + 2) * Dd];
                p3 = myp[(long)(tn + 3) * Dd];
            }
        }
        __syncthreads();
        if (gi == 0) {
            #pragma unroll
            for (int st = 0; st < 4; st++) {
                float yy = 0.f;
                #pragma unroll
                for (int g2 = 0; g2 < 8; g2++) yy += ypart[rb + st][g2][j32];
                y[base + (long)(t + st) * Dd + j] = yy;
            }
        }
    }
    #pragma unroll
    for (int ii = 0; ii < 8; ii++) {
        int i = gi * 8 + ii;
        state_out[(long)((b * Hh + h) * 64 + i) * 64 + j] = S[ii];
    }
}

// ---------------- groupnorm + silu gate ------------------------------------
__global__ void __launch_bounds__(256) gn_gate_kernel(
        const float* __restrict__ y, const float* __restrict__ g,
        const float* __restrict__ lnw, const float* __restrict__ lnb,
        __half* __restrict__ out) {
    long warp = ((long)blockIdx.x * blockDim.x + threadIdx.x) >> 5;
    int lane = threadIdx.x & 31;
    if (warp >= (long)Bb * Tt * Hh) return;
    const float* yp = y + warp * 64;
    float v0 = yp[lane], v1 = yp[lane + 32];
    float s = v0 + v1;
    #pragma unroll
    for (int off = 16; off > 0; off >>= 1) s += __shfl_xor_sync(0xffffffffu, s, off);
    float mean = s * (1.f / 64.f);
    float d0 = v0 - mean, d1 = v1 - mean;
    float vs = d0 * d0 + d1 * d1;
    #pragma unroll
    for (int off = 16; off > 0; off >>= 1) vs += __shfl_xor_sync(0xffffffffu, vs, off);
    float inv = rsqrtf(vs * (1.f / 64.f) + 1e-5f);
    float n0 = fmaf(d0 * inv, lnw[lane], lnb[lane]);
    float n1 = fmaf(d1 * inv, lnw[lane + 32], lnb[lane + 32]);
    float g0 = g[warp * 64 + lane];
    float g1 = g[warp * 64 + lane + 32];
    float s0 = g0 / (1.f + expf(-g0));
    float s1 = g1 / (1.f + expf(-g1));
    out[warp * 64 + lane] = __float2half_rn(s0 * n0);
    out[warp * 64 + lane + 32] = __float2half_rn(s1 * n1);
}

// ---------------- host -----------------------------------------------------
static void* symaddr(const void* s) {
    void* p = nullptr;
    cudaGetSymbolAddress(&p, s);
    return p;
}

extern "C" void kernel_launch(void* const* d_in, const int* in_sizes, int n_in,
                              void* d_out, int out_size) {
    (void)in_sizes; (void)n_in;
    const float* x    = (const float*)d_in[0];
    const float* xw   = (const float*)d_in[1];
    const float* rW   = (const float*)d_in[2];
    const float* kW   = (const float*)d_in[3];
    const float* vW   = (const float*)d_in[4];
    const float* gW   = (const float*)d_in[5];
    const float* la[5] = {(const float*)d_in[6],  (const float*)d_in[9],
                          (const float*)d_in[12], (const float*)d_in[15],
                          (const float*)d_in[18]};
    const float* lb[5] = {(const float*)d_in[7],  (const float*)d_in[10],
                          (const float*)d_in[13], (const float*)d_in[16],
                          (const float*)d_in[19]};
    const float* ll[5] = {(const float*)d_in[8],  (const float*)d_in[11],
                          (const float*)d_in[14], (const float*)d_in[17],
                          (const float*)d_in[20]};
    const float* ln_w = (const float*)d_in[21];
    const float* ln_b = (const float*)d_in[22];
    const float* oW   = (const float*)d_in[23];
    const float* init_state = (const float*)d_in[24];
    const float* u    = (const float*)d_in[25];

    float* out = (float*)d_out;

    float*  p_dx    = (float*)symaddr(g_dx);
    __half* p_lerpx = (__half*)symaddr(g_lerpx);
    __half* p_in    = (__half*)symaddr(g_in);
    __half* p_t1    = (__half*)symaddr(g_t1);
    float*  p_s1p   = (float*)symaddr(g_s1p);
    __half* p_t2    = (__half*)symaddr(g_t2);
    __half* p_laP   = (__half*)symaddr(g_laP);
    __half* p_lbP   = (__half*)symaddr(g_lbP);
    float*  p_llP   = (float*)symaddr(g_llP);
    __half* p_W5    = (__half*)symaddr(g_W5);
    float*  p_w     = (float*)symaddr(g_w);
    float*  p_proj  = (float*)symaddr(g_proj);
    float*  p_y     = (float*)symaddr(g_y);
    __half* p_opre  = (__half*)symaddr(g_opre);
    float*  p_stfb  = (float*)symaddr(g_stfb);

    static cudaStream_t sA = nullptr, sB = nullptr;
    static cudaEvent_t eF = nullptr, eW = nullptr, eL = nullptr,
                       eWG = nullptr, eP = nullptr, eG = nullptr, eB = nullptr;
    if (!sA) {
        cudaStreamCreateWithFlags(&sA, cudaStreamNonBlocking);
        cudaStreamCreateWithFlags(&sB, cudaStreamNonBlocking);
        cudaEventCreateWithFlags(&eF, cudaEventDisableTiming);
        cudaEventCreateWithFlags(&eW, cudaEventDisableTiming);
        cudaEventCreateWithFlags(&eL, cudaEventDisableTiming);
        cudaEventCreateWithFlags(&eWG, cudaEventDisableTiming);
        cudaEventCreateWithFlags(&eP, cudaEventDisableTiming);
        cudaEventCreateWithFlags(&eG, cudaEventDisableTiming);
        cudaEventCreateWithFlags(&eB, cudaEventDisableTiming);
        cudaFuncSetAttribute(gemm_h<0>, cudaFuncAttributeMaxDynamicSharedMemorySize, GSMEM);
        cudaFuncSetAttribute(gemm_h<1>, cudaFuncAttributeMaxDynamicSharedMemorySize, GSMEM);
        cudaFuncSetAttribute(gemm_h<2>, cudaFuncAttributeMaxDynamicSharedMemorySize, GSMEM);
        cudaFuncSetAttribute(gemm_h<3>, cudaFuncAttributeMaxDynamicSharedMemorySize, GSMEM);
    }

    // ---- forks: packs run off the critical path
    cudaEventRecord(eF, 0);
    cudaStreamWaitEvent(sA, eF, 0);
    pack_w_kernel<<<(5 * 1024 * 1024) / 256, 256, 0, sA>>>(rW, kW, vW, gW, oW, p_W5);
    cudaEventRecord(eW, sA);
    cudaStreamWaitEvent(sB, eF, 0);
    pack_la_kernel<<<(384 * 1024) / 256, 256, 0, sB>>>(la[0], la[1], la[2], la[3], la[4], p_laP);
    pack_lb_kernel<<<(5 * 1024 * 64 + 5 * 1024 + 255) / 256, 256, 0, sB>>>(
        lb[0], lb[1], lb[2], lb[3], lb[4], p_lbP,
        ll[0], ll[1], ll[2], ll[3], ll[4], p_llP);
    cudaEventRecord(eB, sB);

    // ---- main chain
    premix_kernel<<<(int)(BTD / 1024), 256>>>(x, xw, p_dx, p_lerpx);

    // lora stage 1, split-K z=2
    cudaStreamWaitEvent(0, eB, 0);
    gemm_h<0><<<dim3(3, 32, 2), 256, GSMEM>>>(
        p_lerpx, 512, 1024, p_laP, 512, 1024, p_s1p, (long)BT * 384, 384,
        nullptr, 0, nullptr, nullptr, 512);
    combine_t1_kernel<<<(BT * 384) / 1024, 256>>>(p_s1p, p_t1);

    // fused lora stage 2 + mix: d-path slice (z=4) FIRST
    gemm_h<2><<<dim3(8, 32, 1), 256, GSMEM>>>(
        p_t1 + 4 * 64, 0, 384, p_lbP + 4 * 65536, 0, 64, p_in + 4 * BTD, 0, 1024,
        p_llP + 4 * 1024, 0, x, p_dx, 64);
    cudaEventRecord(eL, 0);

    // remaining 4 slices (r,k,v,g inputs)
    gemm_h<2><<<dim3(8, 32, 4), 256, GSMEM>>>(
        p_t1, 64, 384, p_lbP, 65536, 64, p_in, BTD, 1024,
        p_llP, 1024, x, p_dx, 64);

    // ---- fork: d-lora second pass (t2, w) on sA
    cudaStreamWaitEvent(sA, eL, 0);
    gemm_h<1><<<dim3(1, 32, 1), 256, GSMEM, sA>>>(
        p_in + 4 * BTD, 0, 1024, p_laP + 256 * 1024, 0, 1024, p_t2, 0, 128,
        nullptr, 0, nullptr, nullptr, 1024);
    gemm_h<3><<<dim3(8, 32, 1), 256, GSMEM, sA>>>(
        p_t2, 0, 128, p_lbP + 4 * 65536, 0, 64, p_w, 0, 1024,
        p_llP + 4 * 1024, 0, nullptr, nullptr, 64);
    cudaEventRecord(eWG, sA);

    // ---- r,k,v projections (need packed weights)
    cudaStreamWaitEvent(0, eW, 0);
    gemm_h<0><<<dim3(8, 32, 3), 256, GSMEM>>>(
        p_in, BTD, 1024, p_W5, 1024 * 1024, 1024, p_proj, BTD, 1024,
        nullptr, 0, nullptr, nullptr, 1024);

    // ---- fork: g projection on sB, parallel with the scan
    cudaEventRecord(eP, 0);
    cudaStreamWaitEvent(sB, eP, 0);
    gemm_h<0><<<dim3(8, 32, 1), 256, GSMEM, sB>>>(
        p_in + 3 * BTD, 0, 1024, p_W5 + 3ll * 1024 * 1024, 0, 1024,
        p_proj + 3 * BTD, 0, 1024, nullptr, 0, nullptr, nullptr, 1024);
    cudaEventRecord(eG, sB);

    // ---- recurrent scan (needs r,k,v + w)
    cudaStreamWaitEvent(0, eWG, 0);
    float* st_out = (out_size >= (int)(BTD + STATE)) ? (out + BTD) : p_stfb;
    scan8_kernel<<<2 * Bb * Hh, 256>>>(p_proj, p_w, p_proj + BTD, p_proj + 2 * BTD,
                                       init_state, u, p_y, st_out);

    // ---- gate (needs g) + output projection
    cudaStreamWaitEvent(0, eG, 0);
    gn_gate_kernel<<<(Bb * Tt * Hh) / 8, 256>>>(p_y, p_proj + 3 * BTD, ln_w, ln_b, p_opre);
    gemm_h<0><<<dim3(8, 32, 1), 256, GSMEM>>>(
        p_opre, 0, 1024, p_W5 + 4ll * 1024 * 1024, 0, 1024, out, 0, 1024,
        nullptr, 0, nullptr, nullptr, 1024);
}

// round 16
// speedup vs baseline: 2.0312x; 1.1570x over previous
#include <cuda_runtime.h>
#include <cuda_fp16.h>
#include <mma.h>
#include <math.h>

#define Bb 4
#define Tt 1024
#define Dd 1024
#define Hh 16
#define HDh 64
#define LR 64
#define BT (Bb*Tt)             /* 4096 */
#define BTD ((long)BT*Dd)      /* 4194304 */
#define STATE (Bb*Hh*HDh*HDh)  /* 262144 */

// ---------------- scratch (device globals; no allocation allowed) ----------
__device__ float  g_dx[BTD];
__device__ __half g_lerpx[BTD];
__device__ __half g_in[5*BTD];
__device__ __half g_t1[(long)BT*384];
__device__ float  g_s1p[2ll*BT*384];   // split-K partials for stage1
__device__ __half g_t2[(long)BT*128];
__device__ __half g_laP[384*1024];
__device__ __half g_lbP[5*1024*64];
__device__ float  g_llP[5*1024];
__device__ __half g_W5[5ll*1024*1024];
__device__ float  g_w[BTD];
__device__ float  g_proj[4*BTD];
__device__ float  g_y[BTD];
__device__ __half g_opre[BTD];
__device__ float  g_stfb[STATE];

__device__ __forceinline__ uint2 h4pack(float a, float b, float c, float d) {
    __half2 p0 = __floats2half2_rn(a, b);
    __half2 p1 = __floats2half2_rn(c, d);
    uint2 r;
    r.x = *reinterpret_cast<unsigned*>(&p0);
    r.y = *reinterpret_cast<unsigned*>(&p1);
    return r;
}

// ---------------- elementwise / pack kernels -------------------------------

__global__ void __launch_bounds__(256) premix_kernel(
        const float* __restrict__ x, const float* __restrict__ xw,
        float* __restrict__ dx, __half* __restrict__ lerpx) {
    long idx = ((long)blockIdx.x * 256 + threadIdx.x) * 4;
    int dd = (int)(idx % Dd);
    long bt = idx / Dd;
    int t = (int)(bt % Tt);
    float4 xv = *(const float4*)&x[idx];
    float4 xp = make_float4(0.f, 0.f, 0.f, 0.f);
    if (t > 0) xp = *(const float4*)&x[idx - Dd];
    float4 wv = *(const float4*)&xw[dd];
    float4 d;
    d.x = xp.x - xv.x; d.y = xp.y - xv.y;
    d.z = xp.z - xv.z; d.w = xp.w - xv.w;
    *(float4*)&dx[idx] = d;
    uint2 o = h4pack(fmaf(d.x, wv.x, xv.x), fmaf(d.y, wv.y, xv.y),
                     fmaf(d.z, wv.z, xv.z), fmaf(d.w, wv.w, xv.w));
    *(uint2*)&lerpx[idx] = o;
}

__global__ void __launch_bounds__(256) pack_la_kernel(
        const float* __restrict__ a0, const float* __restrict__ a1,
        const float* __restrict__ a2, const float* __restrict__ a3,
        const float* __restrict__ a4, __half* __restrict__ dst) {
    long i = (long)blockIdx.x * 256 + threadIdx.x;
    int row = (int)(i >> 10);
    int col = (int)(i & 1023);
    int p = row >> 6;
    float v = 0.f;
    if (p < 5) {
        const float* src = (p == 0) ? a0 : (p == 1) ? a1 : (p == 2) ? a2
                         : (p == 3) ? a3 : a4;
        v = src[(long)(row & 63) * 1024 + col];
    }
    dst[i] = __float2half_rn(v);
}

__global__ void __launch_bounds__(256) pack_lb_kernel(
        const float* __restrict__ b0, const float* __restrict__ b1,
        const float* __restrict__ b2, const float* __restrict__ b3,
        const float* __restrict__ b4, __half* __restrict__ dstb,
        const float* __restrict__ l0, const float* __restrict__ l1,
        const float* __restrict__ l2, const float* __restrict__ l3,
        const float* __restrict__ l4, float* __restrict__ dstl) {
    long i = (long)blockIdx.x * 256 + threadIdx.x;
    if (i < 5ll * 1024 * 64) {
        int p = (int)(i >> 16);
        long r = i & 65535;
        const float* src = (p == 0) ? b0 : (p == 1) ? b1 : (p == 2) ? b2
                         : (p == 3) ? b3 : b4;
        dstb[i] = __float2half_rn(src[r]);
    } else {
        int j = (int)(i - 5ll * 1024 * 64);
        int p = j >> 10;
        int r = j & 1023;
        const float* src = (p == 0) ? l0 : (p == 1) ? l1 : (p == 2) ? l2
                         : (p == 3) ? l3 : l4;
        dstl[j] = src[r];
    }
}

__global__ void __launch_bounds__(256) pack_w_kernel(
        const float* __restrict__ w0, const float* __restrict__ w1,
        const float* __restrict__ w2, const float* __restrict__ w3,
        const float* __restrict__ w4, __half* __restrict__ dst) {
    long i = (long)blockIdx.x * 256 + threadIdx.x;
    int p = (int)(i >> 20);
    long r = i & 1048575;
    const float* src = (p == 0) ? w0 : (p == 1) ? w1 : (p == 2) ? w2
                     : (p == 3) ? w3 : w4;
    dst[i] = __float2half_rn(src[r]);
}

__global__ void __launch_bounds__(256) combine_t1_kernel(
        const float* __restrict__ p, __half* __restrict__ dst) {
    long i = ((long)blockIdx.x * 256 + threadIdx.x) * 4;
    float4 a = *(const float4*)&p[i];
    float4 b = *(const float4*)&p[(long)BT * 384 + i];
    uint2 o = h4pack(tanhf(a.x + b.x), tanhf(a.y + b.y),
                     tanhf(a.z + b.z), tanhf(a.w + b.w));
    *(uint2*)&dst[i] = o;
}

// ---------------- fp16 tensor-core GEMM with fused epilogues ---------------
// PROVEN config: BKK=64, SLDH=72, 2-stage ping-pong, 2 CTAs/SM.
#define BKK 64
#define SLDH 72
#define PIPEH (2*128*SLDH)
#define GSMEM (2*PIPEH*2)

template<int MODE>
__global__ void __launch_bounds__(256) gemm_h(
        const __half* __restrict__ A, long sAz, int lda,
        const __half* __restrict__ W, long sWz, int ldw,
        void* __restrict__ Cv, long sCz, int ldc,
        const float* __restrict__ L, long sLz,
        const float* __restrict__ x, const float* __restrict__ dx,
        int K) {
    using namespace nvcuda;
    extern __shared__ __half sm[];
    const int tid = threadIdx.x;
    const int z = blockIdx.z;
    A += (long)z * sAz;
    W += (long)z * sWz;
    if (MODE >= 2) L += (long)z * sLz;
    float* Cf = (float*)Cv + (long)z * sCz;
    __half* Ch = (__half*)Cv + (long)z * sCz;
    const int bm = blockIdx.y * 128;
    const int bn = blockIdx.x * 128;
    const int r = tid >> 3;
    const int q = (tid & 7) * 8;
    const __half* aP = A + (long)(bm + r) * lda + q;
    const __half* wP = W + (long)(bn + r) * ldw + q;
    unsigned dA = (unsigned)__cvta_generic_to_shared(sm) + (r * SLDH + q) * 2;
    const int wid = tid >> 5;
    const int wy = wid >> 1;
    const int wx = wid & 1;

    wmma::fragment<wmma::accumulator, 16, 16, 16, float> acc[2][4];
    #pragma unroll
    for (int i = 0; i < 2; i++)
        #pragma unroll
        for (int j = 0; j < 4; j++)
            wmma::fill_fragment(acc[i][j], 0.0f);

#define ISSUE(st, k0) do {                                                   \
        unsigned _a = dA + (st) * (PIPEH * 2);                               \
        unsigned _b = _a + 128 * SLDH * 2;                                   \
        _Pragma("unroll")                                                    \
        for (int _i = 0; _i < 4; _i++) {                                     \
            asm volatile("cp.async.cg.shared.global [%0], [%1], 16;\n" ::    \
                "r"(_a + _i * 32 * SLDH * 2),                                \
                "l"(aP + (long)_i * 32 * lda + (k0)));                       \
            asm volatile("cp.async.cg.shared.global [%0], [%1], 16;\n" ::    \
                "r"(_b + _i * 32 * SLDH * 2),                                \
                "l"(wP + (long)_i * 32 * ldw + (k0)));                       \
        }                                                                    \
        asm volatile("cp.async.commit_group;\n");                            \
    } while (0)

    const int nIter = K / BKK;
    ISSUE(0, 0);
    if (nIter > 1) {
        ISSUE(1, BKK);
        asm volatile("cp.async.wait_group 1;\n");
    } else {
        asm volatile("cp.async.wait_group 0;\n");
    }
    __syncthreads();

    for (int it = 0; it < nIter; it++) {
        int s = it & 1;
        const __half* sA = sm + s * PIPEH;
        const __half* sB = sA + 128 * SLDH;
        #pragma unroll
        for (int kk = 0; kk < BKK; kk += 16) {
            wmma::fragment<wmma::matrix_a, 16, 16, 16, __half, wmma::row_major> af[2];
            wmma::fragment<wmma::matrix_b, 16, 16, 16, __half, wmma::col_major> bf[4];
            #pragma unroll
            for (int i = 0; i < 2; i++)
                wmma::load_matrix_sync(af[i], sA + (wy * 32 + i * 16) * SLDH + kk, SLDH);
            #pragma unroll
            for (int j = 0; j < 4; j++)
                wmma::load_matrix_sync(bf[j], sB + (wx * 64 + j * 16) * SLDH + kk, SLDH);
            #pragma unroll
            for (int i = 0; i < 2; i++)
                #pragma unroll
                for (int j = 0; j < 4; j++)
                    wmma::mma_sync(acc[i][j], af[i], bf[j], acc[i][j]);
        }
        __syncthreads();
        if (it + 2 < nIter) {
            ISSUE(s, (it + 2) * BKK);
            asm volatile("cp.async.wait_group 1;\n");
            __syncthreads();
        } else if (it + 1 < nIter) {
            asm volatile("cp.async.wait_group 0;\n");
            __syncthreads();
        }
    }
#undef ISSUE

    if (MODE == 0) {
        #pragma unroll
        for (int i = 0; i < 2; i++)
            #pragma unroll
            for (int j = 0; j < 4; j++)
                wmma::store_matrix_sync(
                    Cf + (long)(bm + wy * 32 + i * 16) * ldc + bn + wx * 64 + j * 16,
                    acc[i][j], ldc, wmma::mem_row_major);
    } else {
        float* smf = reinterpret_cast<float*>(sm);
        __syncthreads();
        #pragma unroll
        for (int i = 0; i < 2; i++)
            #pragma unroll
            for (int j = 0; j < 4; j++)
                wmma::store_matrix_sync(
                    smf + (wy * 32 + i * 16) * 128 + wx * 64 + j * 16,
                    acc[i][j], 128, wmma::mem_row_major);
        __syncthreads();
        int row = tid >> 1;
        int c0 = (tid & 1) * 64;
        long gro = bm + row;
        #pragma unroll
        for (int i = 0; i < 16; i++) {
            int c = c0 + i * 4;
            float4 m = *(float4*)&smf[row * 128 + c];
            if (MODE == 1) {
                uint2 o = h4pack(tanhf(m.x), tanhf(m.y), tanhf(m.z), tanhf(m.w));
                *(uint2*)&Ch[gro * ldc + bn + c] = o;
            } else if (MODE == 2) {
                float4 lv = *(const float4*)&L[bn + c];
                long gi = gro * 1024 + bn + c;
                float4 xv = *(const float4*)&x[gi];
                float4 dv = *(const float4*)&dx[gi];
                uint2 o = h4pack(fmaf(dv.x, m.x + lv.x, xv.x),
                                 fmaf(dv.y, m.y + lv.y, xv.y),
                                 fmaf(dv.z, m.z + lv.z, xv.z),
                                 fmaf(dv.w, m.w + lv.w, xv.w));
                *(uint2*)&Ch[gro * ldc + bn + c] = o;
            } else {
                float4 lv = *(const float4*)&L[bn + c];
                float4 o;
                o.x = expf(-expf(m.x + lv.x));
                o.y = expf(-expf(m.y + lv.y));
                o.z = expf(-expf(m.z + lv.z));
                o.w = expf(-expf(m.w + lv.w));
                *(float4*)&Cf[gro * ldc + bn + c] = o;
            }
        }
    }
}

// ---------------- recurrent scan: 128 CTAs, ONE sync per EIGHT timesteps ---
// 16 rotating smem buffers; iteration it reads octet (it&1)*8+{0..7}, writes
// the other octet. All cross-warp hazards cross exactly one barrier.
__global__ void __launch_bounds__(256) scan16_kernel(
        const float* __restrict__ r, const float* __restrict__ w,
        const float* __restrict__ k, const float* __restrict__ v,
        const float* __restrict__ init_state, const float* __restrict__ u,
        float* __restrict__ y, float* __restrict__ state_out) {
    int cta = blockIdx.x;
    int bh = cta >> 1, jh = cta & 1;
    int b = bh / Hh, h = bh % Hh;
    int tid = threadIdx.x;
    int j32 = tid & 31;
    int gi = tid >> 5;
    int j = jh * 32 + j32;
    __shared__ float sh[16][224];
    __shared__ float ypart[16][8][32];
    float S[8], uu[8];
    #pragma unroll
    for (int ii = 0; ii < 8; ii++) {
        int i = gi * 8 + ii;
        S[ii] = init_state[(long)(h * 64 + i) * 64 + j];
        uu[ii] = u[h * 64 + i];
    }
    long base = (long)b * Tt * Dd + (long)h * 64;
    const float* myp = nullptr;
    if (tid < 64)       myp = r + base + tid;
    else if (tid < 128) myp = w + base + (tid - 64);
    else if (tid < 192) myp = k + base + (tid - 128);
    else if (tid < 224) myp = v + base + jh * 32 + (tid - 192);

    // prologue: stage t=0..7; prefetch t=8..15 (Tt >= 16)
    if (tid < 224) {
        #pragma unroll
        for (int st = 0; st < 8; st++)
            sh[st][tid] = myp[(long)st * Dd];
    }
    __syncthreads();
    float pf[8];
    #pragma unroll
    for (int st = 0; st < 8; st++) pf[st] = 0.f;
    if (tid < 224) {
        #pragma unroll
        for (int st = 0; st < 8; st++)
            pf[st] = myp[(long)(8 + st) * Dd];
    }

    for (int it = 0; it < Tt / 8; it++) {
        int t = it * 8;
        int rb = (it & 1) * 8;          // read octet
        int wb = rb ^ 8;                // write octet
        #pragma unroll
        for (int st = 0; st < 8; st++) {
            const float* s0 = sh[rb + st];
            float vj = s0[192 + j32];
            float acc = 0.f;
            #pragma unroll
            for (int ii = 0; ii < 8; ii++) {
                int i = gi * 8 + ii;
                float kv = s0[128 + i] * vj;
                acc = fmaf(s0[i], fmaf(uu[ii], kv, S[ii]), acc);
                S[ii] = fmaf(s0[64 + i], S[ii], kv);
            }
            ypart[rb + st][gi][j32] = acc;
        }
        if (tid < 224) {
            #pragma unroll
            for (int st = 0; st < 8; st++)
                sh[wb + st][tid] = pf[st];
            int tn = t + 16;
            if (tn < Tt) {
                #pragma unroll
                for (int st = 0; st < 8; st++)
                    pf[st] = myp[(long)(tn + st) * Dd];
            }
        }
        __syncthreads();
        if (gi == 0) {
            #pragma unroll
            for (int st = 0; st < 8; st++) {
                float yy = 0.f;
                #pragma unroll
                for (int g2 = 0; g2 < 8; g2++) yy += ypart[rb + st][g2][j32];
                y[base + (long)(t + st) * Dd + j] = yy;
            }
        }
    }
    #pragma unroll
    for (int ii = 0; ii < 8; ii++) {
        int i = gi * 8 + ii;
        state_out[(long)((b * Hh + h) * 64 + i) * 64 + j] = S[ii];
    }
}

// ---------------- groupnorm + silu gate ------------------------------------
__global__ void __launch_bounds__(256) gn_gate_kernel(
        const float* __restrict__ y, const float* __restrict__ g,
        const float* __restrict__ lnw, const float* __restrict__ lnb,
        __half* __restrict__ out) {
    long warp = ((long)blockIdx.x * blockDim.x + threadIdx.x) >> 5;
    int lane = threadIdx.x & 31;
    if (warp >= (long)Bb * Tt * Hh) return;
    const float* yp = y + warp * 64;
    float v0 = yp[lane], v1 = yp[lane + 32];
    float s = v0 + v1;
    #pragma unroll
    for (int off = 16; off > 0; off >>= 1) s += __shfl_xor_sync(0xffffffffu, s, off);
    float mean = s * (1.f / 64.f);
    float d0 = v0 - mean, d1 = v1 - mean;
    float vs = d0 * d0 + d1 * d1;
    #pragma unroll
    for (int off = 16; off > 0; off >>= 1) vs += __shfl_xor_sync(0xffffffffu, vs, off);
    float inv = rsqrtf(vs * (1.f / 64.f) + 1e-5f);
    float n0 = fmaf(d0 * inv, lnw[lane], lnb[lane]);
    float n1 = fmaf(d1 * inv, lnw[lane + 32], lnb[lane + 32]);
    float g0 = g[warp * 64 + lane];
    float g1 = g[warp * 64 + lane + 32];
    float s0 = g0 / (1.f + expf(-g0));
    float s1 = g1 / (1.f + expf(-g1));
    out[warp * 64 + lane] = __float2half_rn(s0 * n0);
    out[warp * 64 + lane + 32] = __float2half_rn(s1 * n1);
}

// ---------------- host -----------------------------------------------------
static void* symaddr(const void* s) {
    void* p = nullptr;
    cudaGetSymbolAddress(&p, s);
    return p;
}

extern "C" void kernel_launch(void* const* d_in, const int* in_sizes, int n_in,
                              void* d_out, int out_size) {
    (void)in_sizes; (void)n_in;
    const float* x    = (const float*)d_in[0];
    const float* xw   = (const float*)d_in[1];
    const float* rW   = (const float*)d_in[2];
    const float* kW   = (const float*)d_in[3];
    const float* vW   = (const float*)d_in[4];
    const float* gW   = (const float*)d_in[5];
    const float* la[5] = {(const float*)d_in[6],  (const float*)d_in[9],
                          (const float*)d_in[12], (const float*)d_in[15],
                          (const float*)d_in[18]};
    const float* lb[5] = {(const float*)d_in[7],  (const float*)d_in[10],
                          (const float*)d_in[13], (const float*)d_in[16],
                          (const float*)d_in[19]};
    const float* ll[5] = {(const float*)d_in[8],  (const float*)d_in[11],
                          (const float*)d_in[14], (const float*)d_in[17],
                          (const float*)d_in[20]};
    const float* ln_w = (const float*)d_in[21];
    const float* ln_b = (const float*)d_in[22];
    const float* oW   = (const float*)d_in[23];
    const float* init_state = (const float*)d_in[24];
    const float* u    = (const float*)d_in[25];

    float* out = (float*)d_out;

    float*  p_dx    = (float*)symaddr(g_dx);
    __half* p_lerpx = (__half*)symaddr(g_lerpx);
    __half* p_in    = (__half*)symaddr(g_in);
    __half* p_t1    = (__half*)symaddr(g_t1);
    float*  p_s1p   = (float*)symaddr(g_s1p);
    __half* p_t2    = (__half*)symaddr(g_t2);
    __half* p_laP   = (__half*)symaddr(g_laP);
    __half* p_lbP   = (__half*)symaddr(g_lbP);
    float*  p_llP   = (float*)symaddr(g_llP);
    __half* p_W5    = (__half*)symaddr(g_W5);
    float*  p_w     = (float*)symaddr(g_w);
    float*  p_proj  = (float*)symaddr(g_proj);
    float*  p_y     = (float*)symaddr(g_y);
    __half* p_opre  = (__half*)symaddr(g_opre);
    float*  p_stfb  = (float*)symaddr(g_stfb);

    static cudaStream_t sA = nullptr, sB = nullptr;
    static cudaEvent_t eF = nullptr, eW = nullptr, eL = nullptr,
                       eWG = nullptr, eP = nullptr, eG = nullptr, eB = nullptr;
    if (!sA) {
        cudaStreamCreateWithFlags(&sA, cudaStreamNonBlocking);
        cudaStreamCreateWithFlags(&sB, cudaStreamNonBlocking);
        cudaEventCreateWithFlags(&eF, cudaEventDisableTiming);
        cudaEventCreateWithFlags(&eW, cudaEventDisableTiming);
        cudaEventCreateWithFlags(&eL, cudaEventDisableTiming);
        cudaEventCreateWithFlags(&eWG, cudaEventDisableTiming);
        cudaEventCreateWithFlags(&eP, cudaEventDisableTiming);
        cudaEventCreateWithFlags(&eG, cudaEventDisableTiming);
        cudaEventCreateWithFlags(&eB, cudaEventDisableTiming);
        cudaFuncSetAttribute(gemm_h<0>, cudaFuncAttributeMaxDynamicSharedMemorySize, GSMEM);
        cudaFuncSetAttribute(gemm_h<1>, cudaFuncAttributeMaxDynamicSharedMemorySize, GSMEM);
        cudaFuncSetAttribute(gemm_h<2>, cudaFuncAttributeMaxDynamicSharedMemorySize, GSMEM);
        cudaFuncSetAttribute(gemm_h<3>, cudaFuncAttributeMaxDynamicSharedMemorySize, GSMEM);
    }

    // ---- forks: packs run off the critical path
    cudaEventRecord(eF, 0);
    cudaStreamWaitEvent(sA, eF, 0);
    pack_w_kernel<<<(5 * 1024 * 1024) / 256, 256, 0, sA>>>(rW, kW, vW, gW, oW, p_W5);
    cudaEventRecord(eW, sA);
    cudaStreamWaitEvent(sB, eF, 0);
    pack_la_kernel<<<(384 * 1024) / 256, 256, 0, sB>>>(la[0], la[1], la[2], la[3], la[4], p_laP);
    pack_lb_kernel<<<(5 * 1024 * 64 + 5 * 1024 + 255) / 256, 256, 0, sB>>>(
        lb[0], lb[1], lb[2], lb[3], lb[4], p_lbP,
        ll[0], ll[1], ll[2], ll[3], ll[4], p_llP);
    cudaEventRecord(eB, sB);

    // ---- main chain
    premix_kernel<<<(int)(BTD / 1024), 256>>>(x, xw, p_dx, p_lerpx);

    // lora stage 1, split-K z=2
    cudaStreamWaitEvent(0, eB, 0);
    gemm_h<0><<<dim3(3, 32, 2), 256, GSMEM>>>(
        p_lerpx, 512, 1024, p_laP, 512, 1024, p_s1p, (long)BT * 384, 384,
        nullptr, 0, nullptr, nullptr, 512);
    combine_t1_kernel<<<(BT * 384) / 1024, 256>>>(p_s1p, p_t1);

    // fused lora stage 2 + mix: d-path slice (z=4) FIRST
    gemm_h<2><<<dim3(8, 32, 1), 256, GSMEM>>>(
        p_t1 + 4 * 64, 0, 384, p_lbP + 4 * 65536, 0, 64, p_in + 4 * BTD, 0, 1024,
        p_llP + 4 * 1024, 0, x, p_dx, 64);
    cudaEventRecord(eL, 0);

    // remaining 4 slices (r,k,v,g inputs)
    gemm_h<2><<<dim3(8, 32, 4), 256, GSMEM>>>(
        p_t1, 64, 384, p_lbP, 65536, 64, p_in, BTD, 1024,
        p_llP, 1024, x, p_dx, 64);

    // ---- fork: d-lora second pass (t2, w) on sA
    cudaStreamWaitEvent(sA, eL, 0);
    gemm_h<1><<<dim3(1, 32, 1), 256, GSMEM, sA>>>(
        p_in + 4 * BTD, 0, 1024, p_laP + 256 * 1024, 0, 1024, p_t2, 0, 128,
        nullptr, 0, nullptr, nullptr, 1024);
    gemm_h<3><<<dim3(8, 32, 1), 256, GSMEM, sA>>>(
        p_t2, 0, 128, p_lbP + 4 * 65536, 0, 64, p_w, 0, 1024,
        p_llP + 4 * 1024, 0, nullptr, nullptr, 64);
    cudaEventRecord(eWG, sA);

    // ---- r,k,v projections (need packed weights)
    cudaStreamWaitEvent(0, eW, 0);
    gemm_h<0><<<dim3(8, 32, 3), 256, GSMEM>>>(
        p_in, BTD, 1024, p_W5, 1024 * 1024, 1024, p_proj, BTD, 1024,
        nullptr, 0, nullptr, nullptr, 1024);

    // ---- fork: g projection on sB, parallel with the scan
    cudaEventRecord(eP, 0);
    cudaStreamWaitEvent(sB, eP, 0);
    gemm_h<0><<<dim3(8, 32, 1), 256, GSMEM, sB>>>(
        p_in + 3 * BTD, 0, 1024, p_W5 + 3ll * 1024 * 1024, 0, 1024,
        p_proj + 3 * BTD, 0, 1024, nullptr, 0, nullptr, nullptr, 1024);
    cudaEventRecord(eG, sB);

    // ---- recurrent scan (needs r,k,v + w)
    cudaStreamWaitEvent(0, eWG, 0);
    float* st_out = (out_size >= (int)(BTD + STATE)) ? (out + BTD) : p_stfb;
    scan16_kernel<<<2 * Bb * Hh, 256>>>(p_proj, p_w, p_proj + BTD, p_proj + 2 * BTD,
                                        init_state, u, p_y, st_out);

    // ---- gate (needs g) + output projection
    cudaStreamWaitEvent(0, eG, 0);
    gn_gate_kernel<<<(Bb * Tt * Hh) / 8, 256>>>(p_y, p_proj + 3 * BTD, ln_w, ln_b, p_opre);
    gemm_h<0><<<dim3(8, 32, 1), 256, GSMEM>>>(
        p_opre, 0, 1024, p_W5 + 4ll * 1024 * 1024, 0, 1024, out, 0, 1024,
        nullptr, 0, nullptr, nullptr, 1024);
}

// round 17
// speedup vs baseline: 2.0998x; 1.0338x over previous
#include <cuda_runtime.h>
#include <cuda_fp16.h>
#include <mma.h>
#include <math.h>

#define Bb 4
#define Tt 1024
#define Dd 1024
#define Hh 16
#define HDh 64
#define LR 64
#define BT (Bb*Tt)             /* 4096 */
#define BTD ((long)BT*Dd)      /* 4194304 */
#define STATE (Bb*Hh*HDh*HDh)  /* 262144 */

// ---------------- scratch (device globals; no allocation allowed) ----------
__device__ float  g_dx[BTD];
__device__ __half g_lerpx[BTD];
__device__ __half g_in[5*BTD];
__device__ __half g_t1[(long)BT*384];
__device__ float  g_s1p[2ll*BT*384];   // split-K partials for stage1
__device__ __half g_t2[(long)BT*128];
__device__ __half g_laP[384*1024];
__device__ __half g_lbP[5*1024*64];
__device__ float  g_llP[5*1024];
__device__ __half g_W5[5ll*1024*1024];
__device__ float  g_w[BTD];
__device__ float  g_proj[4*BTD];
__device__ float  g_y[BTD];
__device__ __half g_opre[BTD];
__device__ float  g_stfb[STATE];

__device__ __forceinline__ uint2 h4pack(float a, float b, float c, float d) {
    __half2 p0 = __floats2half2_rn(a, b);
    __half2 p1 = __floats2half2_rn(c, d);
    uint2 r;
    r.x = *reinterpret_cast<unsigned*>(&p0);
    r.y = *reinterpret_cast<unsigned*>(&p1);
    return r;
}

// ---------------- elementwise / pack kernels -------------------------------

__global__ void __launch_bounds__(256) premix_kernel(
        const float* __restrict__ x, const float* __restrict__ xw,
        float* __restrict__ dx, __half* __restrict__ lerpx) {
    long idx = ((long)blockIdx.x * 256 + threadIdx.x) * 4;
    int dd = (int)(idx % Dd);
    long bt = idx / Dd;
    int t = (int)(bt % Tt);
    float4 xv = *(const float4*)&x[idx];
    float4 xp = make_float4(0.f, 0.f, 0.f, 0.f);
    if (t > 0) xp = *(const float4*)&x[idx - Dd];
    float4 wv = *(const float4*)&xw[dd];
    float4 d;
    d.x = xp.x - xv.x; d.y = xp.y - xv.y;
    d.z = xp.z - xv.z; d.w = xp.w - xv.w;
    *(float4*)&dx[idx] = d;
    uint2 o = h4pack(fmaf(d.x, wv.x, xv.x), fmaf(d.y, wv.y, xv.y),
                     fmaf(d.z, wv.z, xv.z), fmaf(d.w, wv.w, xv.w));
    *(uint2*)&lerpx[idx] = o;
}

__global__ void __launch_bounds__(256) pack_la_kernel(
        const float* __restrict__ a0, const float* __restrict__ a1,
        const float* __restrict__ a2, const float* __restrict__ a3,
        const float* __restrict__ a4, __half* __restrict__ dst) {
    long i = (long)blockIdx.x * 256 + threadIdx.x;
    int row = (int)(i >> 10);
    int col = (int)(i & 1023);
    int p = row >> 6;
    float v = 0.f;
    if (p < 5) {
        const float* src = (p == 0) ? a0 : (p == 1) ? a1 : (p == 2) ? a2
                         : (p == 3) ? a3 : a4;
        v = src[(long)(row & 63) * 1024 + col];
    }
    dst[i] = __float2half_rn(v);
}

__global__ void __launch_bounds__(256) pack_lb_kernel(
        const float* __restrict__ b0, const float* __restrict__ b1,
        const float* __restrict__ b2, const float* __restrict__ b3,
        const float* __restrict__ b4, __half* __restrict__ dstb,
        const float* __restrict__ l0, const float* __restrict__ l1,
        const float* __restrict__ l2, const float* __restrict__ l3,
        const float* __restrict__ l4, float* __restrict__ dstl) {
    long i = (long)blockIdx.x * 256 + threadIdx.x;
    if (i < 5ll * 1024 * 64) {
        int p = (int)(i >> 16);
        long r = i & 65535;
        const float* src = (p == 0) ? b0 : (p == 1) ? b1 : (p == 2) ? b2
                         : (p == 3) ? b3 : b4;
        dstb[i] = __float2half_rn(src[r]);
    } else {
        int j = (int)(i - 5ll * 1024 * 64);
        int p = j >> 10;
        int r = j & 1023;
        const float* src = (p == 0) ? l0 : (p == 1) ? l1 : (p == 2) ? l2
                         : (p == 3) ? l3 : l4;
        dstl[j] = src[r];
    }
}

__global__ void __launch_bounds__(256) pack_w_kernel(
        const float* __restrict__ w0, const float* __restrict__ w1,
        const float* __restrict__ w2, const float* __restrict__ w3,
        const float* __restrict__ w4, __half* __restrict__ dst) {
    long i = (long)blockIdx.x * 256 + threadIdx.x;
    int p = (int)(i >> 20);
    long r = i & 1048575;
    const float* src = (p == 0) ? w0 : (p == 1) ? w1 : (p == 2) ? w2
                     : (p == 3) ? w3 : w4;
    dst[i] = __float2half_rn(src[r]);
}

__global__ void __launch_bounds__(256) combine_t1_kernel(
        const float* __restrict__ p, __half* __restrict__ dst) {
    long i = ((long)blockIdx.x * 256 + threadIdx.x) * 4;
    float4 a = *(const float4*)&p[i];
    float4 b = *(const float4*)&p[(long)BT * 384 + i];
    uint2 o = h4pack(tanhf(a.x + b.x), tanhf(a.y + b.y),
                     tanhf(a.z + b.z), tanhf(a.w + b.w));
    *(uint2*)&dst[i] = o;
}

// ---------------- fp16 tensor-core GEMM with fused epilogues ---------------
// PROVEN config: BKK=64, SLDH=72, 2-stage ping-pong, 2 CTAs/SM.
#define BKK 64
#define SLDH 72
#define PIPEH (2*128*SLDH)
#define GSMEM (2*PIPEH*2)

template<int MODE>
__global__ void __launch_bounds__(256) gemm_h(
        const __half* __restrict__ A, long sAz, int lda,
        const __half* __restrict__ W, long sWz, int ldw,
        void* __restrict__ Cv, long sCz, int ldc,
        const float* __restrict__ L, long sLz,
        const float* __restrict__ x, const float* __restrict__ dx,
        int K) {
    using namespace nvcuda;
    extern __shared__ __half sm[];
    const int tid = threadIdx.x;
    const int z = blockIdx.z;
    A += (long)z * sAz;
    W += (long)z * sWz;
    if (MODE >= 2) L += (long)z * sLz;
    float* Cf = (float*)Cv + (long)z * sCz;
    __half* Ch = (__half*)Cv + (long)z * sCz;
    const int bm = blockIdx.y * 128;
    const int bn = blockIdx.x * 128;
    const int r = tid >> 3;
    const int q = (tid & 7) * 8;
    const __half* aP = A + (long)(bm + r) * lda + q;
    const __half* wP = W + (long)(bn + r) * ldw + q;
    unsigned dA = (unsigned)__cvta_generic_to_shared(sm) + (r * SLDH + q) * 2;
    const int wid = tid >> 5;
    const int wy = wid >> 1;
    const int wx = wid & 1;

    wmma::fragment<wmma::accumulator, 16, 16, 16, float> acc[2][4];
    #pragma unroll
    for (int i = 0; i < 2; i++)
        #pragma unroll
        for (int j = 0; j < 4; j++)
            wmma::fill_fragment(acc[i][j], 0.0f);

#define ISSUE(st, k0) do {                                                   \
        unsigned _a = dA + (st) * (PIPEH * 2);                               \
        unsigned _b = _a + 128 * SLDH * 2;                                   \
        _Pragma("unroll")                                                    \
        for (int _i = 0; _i < 4; _i++) {                                     \
            asm volatile("cp.async.cg.shared.global [%0], [%1], 16;\n" ::    \
                "r"(_a + _i * 32 * SLDH * 2),                                \
                "l"(aP + (long)_i * 32 * lda + (k0)));                       \
            asm volatile("cp.async.cg.shared.global [%0], [%1], 16;\n" ::    \
                "r"(_b + _i * 32 * SLDH * 2),                                \
                "l"(wP + (long)_i * 32 * ldw + (k0)));                       \
        }                                                                    \
        asm volatile("cp.async.commit_group;\n");                            \
    } while (0)

    const int nIter = K / BKK;
    ISSUE(0, 0);
    if (nIter > 1) {
        ISSUE(1, BKK);
        asm volatile("cp.async.wait_group 1;\n");
    } else {
        asm volatile("cp.async.wait_group 0;\n");
    }
    __syncthreads();

    for (int it = 0; it < nIter; it++) {
        int s = it & 1;
        const __half* sA = sm + s * PIPEH;
        const __half* sB = sA + 128 * SLDH;
        #pragma unroll
        for (int kk = 0; kk < BKK; kk += 16) {
            wmma::fragment<wmma::matrix_a, 16, 16, 16, __half, wmma::row_major> af[2];
            wmma::fragment<wmma::matrix_b, 16, 16, 16, __half, wmma::col_major> bf[4];
            #pragma unroll
            for (int i = 0; i < 2; i++)
                wmma::load_matrix_sync(af[i], sA + (wy * 32 + i * 16) * SLDH + kk, SLDH);
            #pragma unroll
            for (int j = 0; j < 4; j++)
                wmma::load_matrix_sync(bf[j], sB + (wx * 64 + j * 16) * SLDH + kk, SLDH);
            #pragma unroll
            for (int i = 0; i < 2; i++)
                #pragma unroll
                for (int j = 0; j < 4; j++)
                    wmma::mma_sync(acc[i][j], af[i], bf[j], acc[i][j]);
        }
        __syncthreads();
        if (it + 2 < nIter) {
            ISSUE(s, (it + 2) * BKK);
            asm volatile("cp.async.wait_group 1;\n");
            __syncthreads();
        } else if (it + 1 < nIter) {
            asm volatile("cp.async.wait_group 0;\n");
            __syncthreads();
        }
    }
#undef ISSUE

    if (MODE == 0) {
        #pragma unroll
        for (int i = 0; i < 2; i++)
            #pragma unroll
            for (int j = 0; j < 4; j++)
                wmma::store_matrix_sync(
                    Cf + (long)(bm + wy * 32 + i * 16) * ldc + bn + wx * 64 + j * 16,
                    acc[i][j], ldc, wmma::mem_row_major);
    } else {
        float* smf = reinterpret_cast<float*>(sm);
        __syncthreads();
        #pragma unroll
        for (int i = 0; i < 2; i++)
            #pragma unroll
            for (int j = 0; j < 4; j++)
                wmma::store_matrix_sync(
                    smf + (wy * 32 + i * 16) * 128 + wx * 64 + j * 16,
                    acc[i][j], 128, wmma::mem_row_major);
        __syncthreads();
        int row = tid >> 1;
        int c0 = (tid & 1) * 64;
        long gro = bm + row;
        #pragma unroll
        for (int i = 0; i < 16; i++) {
            int c = c0 + i * 4;
            float4 m = *(float4*)&smf[row * 128 + c];
            if (MODE == 1) {
                uint2 o = h4pack(tanhf(m.x), tanhf(m.y), tanhf(m.z), tanhf(m.w));
                *(uint2*)&Ch[gro * ldc + bn + c] = o;
            } else if (MODE == 2) {
                float4 lv = *(const float4*)&L[bn + c];
                long gi = gro * 1024 + bn + c;
                float4 xv = *(const float4*)&x[gi];
                float4 dv = *(const float4*)&dx[gi];
                uint2 o = h4pack(fmaf(dv.x, m.x + lv.x, xv.x),
                                 fmaf(dv.y, m.y + lv.y, xv.y),
                                 fmaf(dv.z, m.z + lv.z, xv.z),
                                 fmaf(dv.w, m.w + lv.w, xv.w));
                *(uint2*)&Ch[gro * ldc + bn + c] = o;
            } else {
                float4 lv = *(const float4*)&L[bn + c];
                float4 o;
                o.x = expf(-expf(m.x + lv.x));
                o.y = expf(-expf(m.y + lv.y));
                o.z = expf(-expf(m.z + lv.z));
                o.w = expf(-expf(m.w + lv.w));
                *(float4*)&Cf[gro * ldc + bn + c] = o;
            }
        }
    }
}

// ---------------- recurrent scan: 128 CTAs, ONE sync per 16 timesteps ------
// 32 rotating smem buffers (dynamic smem, 61.5KB); iteration it reads half
// (it&1)*16+{0..15}, writes the other half. All cross-warp hazards cross
// exactly one barrier.
#define SCAN_STEPS 16
#define SCAN_SH (2*SCAN_STEPS*224)                  /* floats */
#define SCAN_SMEM ((SCAN_SH + 2*SCAN_STEPS*8*32)*4) /* bytes = 61440 */

__global__ void __launch_bounds__(256) scan32_kernel(
        const float* __restrict__ r, const float* __restrict__ w,
        const float* __restrict__ k, const float* __restrict__ v,
        const float* __restrict__ init_state, const float* __restrict__ u,
        float* __restrict__ y, float* __restrict__ state_out) {
    extern __shared__ float dsm[];
    float* sh = dsm;                        // [32][224]
    float* yp = dsm + SCAN_SH;              // [32][8][32]
    int cta = blockIdx.x;
    int bh = cta >> 1, jh = cta & 1;
    int b = bh / Hh, h = bh % Hh;
    int tid = threadIdx.x;
    int j32 = tid & 31;
    int gi = tid >> 5;
    int j = jh * 32 + j32;
    float S[8], uu[8];
    #pragma unroll
    for (int ii = 0; ii < 8; ii++) {
        int i = gi * 8 + ii;
        S[ii] = init_state[(long)(h * 64 + i) * 64 + j];
        uu[ii] = u[h * 64 + i];
    }
    long base = (long)b * Tt * Dd + (long)h * 64;
    const float* myp = nullptr;
    if (tid < 64)       myp = r + base + tid;
    else if (tid < 128) myp = w + base + (tid - 64);
    else if (tid < 192) myp = k + base + (tid - 128);
    else if (tid < 224) myp = v + base + jh * 32 + (tid - 192);

    // prologue: stage t=0..15; prefetch t=16..31 (Tt >= 32)
    if (tid < 224) {
        #pragma unroll
        for (int st = 0; st < SCAN_STEPS; st++)
            sh[st * 224 + tid] = myp[(long)st * Dd];
    }
    __syncthreads();
    float pf[SCAN_STEPS];
    #pragma unroll
    for (int st = 0; st < SCAN_STEPS; st++) pf[st] = 0.f;
    if (tid < 224) {
        #pragma unroll
        for (int st = 0; st < SCAN_STEPS; st++)
            pf[st] = myp[(long)(SCAN_STEPS + st) * Dd];
    }

    for (int it = 0; it < Tt / SCAN_STEPS; it++) {
        int t = it * SCAN_STEPS;
        int rb = (it & 1) * SCAN_STEPS;     // read half
        int wb = rb ^ SCAN_STEPS;           // write half
        #pragma unroll
        for (int st = 0; st < SCAN_STEPS; st++) {
            const float* s0 = sh + (rb + st) * 224;
            float vj = s0[192 + j32];
            float acc = 0.f;
            #pragma unroll
            for (int ii = 0; ii < 8; ii++) {
                int i = gi * 8 + ii;
                float kv = s0[128 + i] * vj;
                acc = fmaf(s0[i], fmaf(uu[ii], kv, S[ii]), acc);
                S[ii] = fmaf(s0[64 + i], S[ii], kv);
            }
            yp[((rb + st) * 8 + gi) * 32 + j32] = acc;
        }
        if (tid < 224) {
            #pragma unroll
            for (int st = 0; st < SCAN_STEPS; st++)
                sh[(wb + st) * 224 + tid] = pf[st];
            int tn = t + 2 * SCAN_STEPS;
            if (tn < Tt) {
                #pragma unroll
                for (int st = 0; st < SCAN_STEPS; st++)
                    pf[st] = myp[(long)(tn + st) * Dd];
            }
        }
        __syncthreads();
        if (gi == 0) {
            #pragma unroll
            for (int st = 0; st < SCAN_STEPS; st++) {
                float yy = 0.f;
                #pragma unroll
                for (int g2 = 0; g2 < 8; g2++)
                    yy += yp[((rb + st) * 8 + g2) * 32 + j32];
                y[base + (long)(t + st) * Dd + j] = yy;
            }
        }
    }
    #pragma unroll
    for (int ii = 0; ii < 8; ii++) {
        int i = gi * 8 + ii;
        state_out[(long)((b * Hh + h) * 64 + i) * 64 + j] = S[ii];
    }
}

// ---------------- groupnorm + silu gate ------------------------------------
__global__ void __launch_bounds__(256) gn_gate_kernel(
        const float* __restrict__ y, const float* __restrict__ g,
        const float* __restrict__ lnw, const float* __restrict__ lnb,
        __half* __restrict__ out) {
    long warp = ((long)blockIdx.x * blockDim.x + threadIdx.x) >> 5;
    int lane = threadIdx.x & 31;
    if (warp >= (long)Bb * Tt * Hh) return;
    const float* ypr = y + warp * 64;
    float v0 = ypr[lane], v1 = ypr[lane + 32];
    float s = v0 + v1;
    #pragma unroll
    for (int off = 16; off > 0; off >>= 1) s += __shfl_xor_sync(0xffffffffu, s, off);
    float mean = s * (1.f / 64.f);
    float d0 = v0 - mean, d1 = v1 - mean;
    float vs = d0 * d0 + d1 * d1;
    #pragma unroll
    for (int off = 16; off > 0; off >>= 1) vs += __shfl_xor_sync(0xffffffffu, vs, off);
    float inv = rsqrtf(vs * (1.f / 64.f) + 1e-5f);
    float n0 = fmaf(d0 * inv, lnw[lane], lnb[lane]);
    float n1 = fmaf(d1 * inv, lnw[lane + 32], lnb[lane + 32]);
    float g0 = g[warp * 64 + lane];
    float g1 = g[warp * 64 + lane + 32];
    float s0 = g0 / (1.f + expf(-g0));
    float s1 = g1 / (1.f + expf(-g1));
    out[warp * 64 + lane] = __float2half_rn(s0 * n0);
    out[warp * 64 + lane + 32] = __float2half_rn(s1 * n1);
}

// ---------------- host -----------------------------------------------------
static void* symaddr(const void* s) {
    void* p = nullptr;
    cudaGetSymbolAddress(&p, s);
    return p;
}

extern "C" void kernel_launch(void* const* d_in, const int* in_sizes, int n_in,
                              void* d_out, int out_size) {
    (void)in_sizes; (void)n_in;
    const float* x    = (const float*)d_in[0];
    const float* xw   = (const float*)d_in[1];
    const float* rW   = (const float*)d_in[2];
    const float* kW   = (const float*)d_in[3];
    const float* vW   = (const float*)d_in[4];
    const float* gW   = (const float*)d_in[5];
    const float* la[5] = {(const float*)d_in[6],  (const float*)d_in[9],
                          (const float*)d_in[12], (const float*)d_in[15],
                          (const float*)d_in[18]};
    const float* lb[5] = {(const float*)d_in[7],  (const float*)d_in[10],
                          (const float*)d_in[13], (const float*)d_in[16],
                          (const float*)d_in[19]};
    const float* ll[5] = {(const float*)d_in[8],  (const float*)d_in[11],
                          (const float*)d_in[14], (const float*)d_in[17],
                          (const float*)d_in[20]};
    const float* ln_w = (const float*)d_in[21];
    const float* ln_b = (const float*)d_in[22];
    const float* oW   = (const float*)d_in[23];
    const float* init_state = (const float*)d_in[24];
    const float* u    = (const float*)d_in[25];

    float* out = (float*)d_out;

    float*  p_dx    = (float*)symaddr(g_dx);
    __half* p_lerpx = (__half*)symaddr(g_lerpx);
    __half* p_in    = (__half*)symaddr(g_in);
    __half* p_t1    = (__half*)symaddr(g_t1);
    float*  p_s1p   = (float*)symaddr(g_s1p);
    __half* p_t2    = (__half*)symaddr(g_t2);
    __half* p_laP   = (__half*)symaddr(g_laP);
    __half* p_lbP   = (__half*)symaddr(g_lbP);
    float*  p_llP   = (float*)symaddr(g_llP);
    __half* p_W5    = (__half*)symaddr(g_W5);
    float*  p_w     = (float*)symaddr(g_w);
    float*  p_proj  = (float*)symaddr(g_proj);
    float*  p_y     = (float*)symaddr(g_y);
    __half* p_opre  = (__half*)symaddr(g_opre);
    float*  p_stfb  = (float*)symaddr(g_stfb);

    static cudaStream_t sA = nullptr, sB = nullptr;
    static cudaEvent_t eF = nullptr, eW = nullptr, eL = nullptr,
                       eWG = nullptr, eP = nullptr, eG = nullptr, eB = nullptr;
    if (!sA) {
        cudaStreamCreateWithFlags(&sA, cudaStreamNonBlocking);
        cudaStreamCreateWithFlags(&sB, cudaStreamNonBlocking);
        cudaEventCreateWithFlags(&eF, cudaEventDisableTiming);
        cudaEventCreateWithFlags(&eW, cudaEventDisableTiming);
        cudaEventCreateWithFlags(&eL, cudaEventDisableTiming);
        cudaEventCreateWithFlags(&eWG, cudaEventDisableTiming);
        cudaEventCreateWithFlags(&eP, cudaEventDisableTiming);
        cudaEventCreateWithFlags(&eG, cudaEventDisableTiming);
        cudaEventCreateWithFlags(&eB, cudaEventDisableTiming);
        cudaFuncSetAttribute(gemm_h<0>, cudaFuncAttributeMaxDynamicSharedMemorySize, GSMEM);
        cudaFuncSetAttribute(gemm_h<1>, cudaFuncAttributeMaxDynamicSharedMemorySize, GSMEM);
        cudaFuncSetAttribute(gemm_h<2>, cudaFuncAttributeMaxDynamicSharedMemorySize, GSMEM);
        cudaFuncSetAttribute(gemm_h<3>, cudaFuncAttributeMaxDynamicSharedMemorySize, GSMEM);
        cudaFuncSetAttribute(scan32_kernel, cudaFuncAttributeMaxDynamicSharedMemorySize, SCAN_SMEM);
    }

    // ---- forks: packs run off the critical path
    cudaEventRecord(eF, 0);
    cudaStreamWaitEvent(sA, eF, 0);
    pack_w_kernel<<<(5 * 1024 * 1024) / 256, 256, 0, sA>>>(rW, kW, vW, gW, oW, p_W5);
    cudaEventRecord(eW, sA);
    cudaStreamWaitEvent(sB, eF, 0);
    pack_la_kernel<<<(384 * 1024) / 256, 256, 0, sB>>>(la[0], la[1], la[2], la[3], la[4], p_laP);
    pack_lb_kernel<<<(5 * 1024 * 64 + 5 * 1024 + 255) / 256, 256, 0, sB>>>(
        lb[0], lb[1], lb[2], lb[3], lb[4], p_lbP,
        ll[0], ll[1], ll[2], ll[3], ll[4], p_llP);
    cudaEventRecord(eB, sB);

    // ---- main chain
    premix_kernel<<<(int)(BTD / 1024), 256>>>(x, xw, p_dx, p_lerpx);

    // lora stage 1, split-K z=2
    cudaStreamWaitEvent(0, eB, 0);
    gemm_h<0><<<dim3(3, 32, 2), 256, GSMEM>>>(
        p_lerpx, 512, 1024, p_laP, 512, 1024, p_s1p, (long)BT * 384, 384,
        nullptr, 0, nullptr, nullptr, 512);
    combine_t1_kernel<<<(BT * 384) / 1024, 256>>>(p_s1p, p_t1);

    // fused lora stage 2 + mix: d-path slice (z=4) FIRST
    gemm_h<2><<<dim3(8, 32, 1), 256, GSMEM>>>(
        p_t1 + 4 * 64, 0, 384, p_lbP + 4 * 65536, 0, 64, p_in + 4 * BTD, 0, 1024,
        p_llP + 4 * 1024, 0, x, p_dx, 64);
    cudaEventRecord(eL, 0);

    // remaining 4 slices (r,k,v,g inputs)
    gemm_h<2><<<dim3(8, 32, 4), 256, GSMEM>>>(
        p_t1, 64, 384, p_lbP, 65536, 64, p_in, BTD, 1024,
        p_llP, 1024, x, p_dx, 64);

    // ---- fork: d-lora second pass (t2, w) on sA
    cudaStreamWaitEvent(sA, eL, 0);
    gemm_h<1><<<dim3(1, 32, 1), 256, GSMEM, sA>>>(
        p_in + 4 * BTD, 0, 1024, p_laP + 256 * 1024, 0, 1024, p_t2, 0, 128,
        nullptr, 0, nullptr, nullptr, 1024);
    gemm_h<3><<<dim3(8, 32, 1), 256, GSMEM, sA>>>(
        p_t2, 0, 128, p_lbP + 4 * 65536, 0, 64, p_w, 0, 1024,
        p_llP + 4 * 1024, 0, nullptr, nullptr, 64);
    cudaEventRecord(eWG, sA);

    // ---- r,k,v projections (need packed weights)
    cudaStreamWaitEvent(0, eW, 0);
    gemm_h<0><<<dim3(8, 32, 3), 256, GSMEM>>>(
        p_in, BTD, 1024, p_W5, 1024 * 1024, 1024, p_proj, BTD, 1024,
        nullptr, 0, nullptr, nullptr, 1024);

    // ---- fork: g projection on sB, parallel with the scan
    cudaEventRecord(eP, 0);
    cudaStreamWaitEvent(sB, eP, 0);
    gemm_h<0><<<dim3(8, 32, 1), 256, GSMEM, sB>>>(
        p_in + 3 * BTD, 0, 1024, p_W5 + 3ll * 1024 * 1024, 0, 1024,
        p_proj + 3 * BTD, 0, 1024, nullptr, 0, nullptr, nullptr, 1024);
    cudaEventRecord(eG, sB);

    // ---- recurrent scan (needs r,k,v + w)
    cudaStreamWaitEvent(0, eWG, 0);
    float* st_out = (out_size >= (int)(BTD + STATE)) ? (out + BTD) : p_stfb;
    scan32_kernel<<<2 * Bb * Hh, 256, SCAN_SMEM>>>(
        p_proj, p_w, p_proj + BTD, p_proj + 2 * BTD,
        init_state, u, p_y, st_out);

    // ---- gate (needs g) + output projection
    cudaStreamWaitEvent(0, eG, 0);
    gn_gate_kernel<<<(Bb * Tt * Hh) / 8, 256>>>(p_y, p_proj + 3 * BTD, ln_w, ln_b, p_opre);
    gemm_h<0><<<dim3(8, 32, 1), 256, GSMEM>>>(
        p_opre, 0, 1024, p_W5 + 4ll * 1024 * 1024, 0, 1024, out, 0, 1024,
        nullptr, 0, nullptr, nullptr, 1024);
}